// round 12
// baseline (speedup 1.0000x reference)
#include <cuda_runtime.h>
#include <cuda_bf16.h>
#include <cuda_fp8.h>
#include <math.h>
#include <stdint.h>

#define BATCH   2
#define SEQ     2048
#define DMODEL  2048
#define NHEADS  32
#define HDIM    64
#define KVHEADS 8
#define MROWS   (BATCH*SEQ)          // 4096

// ---------------- scratch (device globals; no allocation allowed) ----------
__device__ float g_Q[MROWS * NHEADS * HDIM];
__device__ float g_K[MROWS * KVHEADS * HDIM];
__device__ float g_V[MROWS * KVHEADS * HDIM];
__device__ float g_freqs[32];

// bf16 planes (hi/lo)
__device__ __nv_bfloat16 g_xh [MROWS * DMODEL];
__device__ __nv_bfloat16 g_xl [MROWS * DMODEL];
__device__ __nv_bfloat16 g_Wqh[DMODEL * 2048];
__device__ __nv_bfloat16 g_Wql[DMODEL * 2048];
__device__ __nv_bfloat16 g_Wkh[DMODEL * 512];
__device__ __nv_bfloat16 g_Wkl[DMODEL * 512];
__device__ __nv_bfloat16 g_Wvh[DMODEL * 512];
__device__ __nv_bfloat16 g_Wvl[DMODEL * 512];
__device__ __nv_bfloat16 g_Woh[2048 * DMODEL];
__device__ __nv_bfloat16 g_Wol[2048 * DMODEL];
__device__ __nv_bfloat16 g_Qh [MROWS * 2048];
__device__ __nv_bfloat16 g_Ql [MROWS * 2048];
__device__ __nv_bfloat16 g_Kh [MROWS * 512];
__device__ __nv_bfloat16 g_Kl [MROWS * 512];
__device__ __nv_bfloat16 g_Vh [MROWS * 512];
__device__ __nv_bfloat16 g_Vl [MROWS * 512];
__device__ __nv_bfloat16 g_Oh [MROWS * 2048];
__device__ __nv_bfloat16 g_Ol [MROWS * 2048];

// fp8 planes for GEMM corrections. A-side: [M,K]; weights TRANSPOSED [N,K].
__device__ uint8_t g_x8h [MROWS * DMODEL];
__device__ uint8_t g_x8l [MROWS * DMODEL];
__device__ uint8_t g_Wq8h[2048 * DMODEL];
__device__ uint8_t g_Wq8l[2048 * DMODEL];
__device__ uint8_t g_Wk8h[512 * DMODEL];
__device__ uint8_t g_Wk8l[512 * DMODEL];
__device__ uint8_t g_Wv8h[512 * DMODEL];
__device__ uint8_t g_Wv8l[512 * DMODEL];
__device__ uint8_t g_Wo8h[2048 * DMODEL];
__device__ uint8_t g_Wo8l[2048 * DMODEL];
__device__ uint8_t g_O8h [MROWS * 2048];
__device__ uint8_t g_O8l [MROWS * 2048];

// ---------------- RoPE frequency table -------------------------------------
__global__ void init_freqs_kernel() {
    int i = threadIdx.x;
    g_freqs[i] = (float)exp2(-(double)i * (13.287712379549449 / 32.0));
}

__device__ __forceinline__ uint8_t f2e4m3(float f) {
    return (uint8_t)__nv_cvt_float_to_fp8(f, __NV_SATFINITE, __NV_E4M3);
}

// ---------------- fp32 -> (hi, lo) bf16 split -------------------------------
__global__ void __launch_bounds__(256) split_kernel(
    const float* __restrict__ src, __nv_bfloat16* __restrict__ hi,
    __nv_bfloat16* __restrict__ lo, int n4)
{
    const int i = blockIdx.x * blockDim.x + threadIdx.x;
    if (i >= n4) return;
    const float4 f = ((const float4*)src)[i];
    __nv_bfloat16 h[4], l[4];
    const float fv[4] = {f.x, f.y, f.z, f.w};
#pragma unroll
    for (int k = 0; k < 4; k++) {
        h[k] = __float2bfloat16(fv[k]);
        l[k] = __float2bfloat16(fv[k] - __bfloat162float(h[k]));
    }
    *(uint2*)(hi + 4 * (size_t)i) = *(uint2*)h;
    *(uint2*)(lo + 4 * (size_t)i) = *(uint2*)l;
}

// ---------------- fp32 -> fp8 hi/lo planes (A-side, row-major) --------------
// h8 = e4m3(4*bf16hi(x)), l8 = e4m3(1024*(x - bf16hi(x)))
__global__ void __launch_bounds__(256) fp8a_kernel(
    const float* __restrict__ src, uint8_t* __restrict__ h8,
    uint8_t* __restrict__ l8, int n4)
{
    const int i = blockIdx.x * blockDim.x + threadIdx.x;
    if (i >= n4) return;
    const float4 f = ((const float4*)src)[i];
    const float fv[4] = {f.x, f.y, f.z, f.w};
    uint8_t hb[4], lb[4];
#pragma unroll
    for (int k = 0; k < 4; k++) {
        const float hf = __bfloat162float(__float2bfloat16(fv[k]));
        hb[k] = f2e4m3(4.0f * hf);
        lb[k] = f2e4m3(1024.0f * (fv[k] - hf));
    }
    *(unsigned*)(h8 + 4 * (size_t)i) = *(unsigned*)hb;
    *(unsigned*)(l8 + 4 * (size_t)i) = *(unsigned*)lb;
}

// ---------------- bf16 hi/lo planes -> fp8 planes (for O) -------------------
__global__ void __launch_bounds__(256) fp8o_kernel(
    const __nv_bfloat16* __restrict__ hi, const __nv_bfloat16* __restrict__ lo,
    uint8_t* __restrict__ h8, uint8_t* __restrict__ l8, int n4)
{
    const int i = blockIdx.x * blockDim.x + threadIdx.x;
    if (i >= n4) return;
    uint2 hv = *(const uint2*)(hi + 4 * (size_t)i);
    uint2 lv = *(const uint2*)(lo + 4 * (size_t)i);
    const __nv_bfloat16* hp = (const __nv_bfloat16*)&hv;
    const __nv_bfloat16* lp = (const __nv_bfloat16*)&lv;
    uint8_t hb[4], lb[4];
#pragma unroll
    for (int k = 0; k < 4; k++) {
        hb[k] = f2e4m3(4.0f * __bfloat162float(hp[k]));
        lb[k] = f2e4m3(1024.0f * __bfloat162float(lp[k]));
    }
    *(unsigned*)(h8 + 4 * (size_t)i) = *(unsigned*)hb;
    *(unsigned*)(l8 + 4 * (size_t)i) = *(unsigned*)lb;
}

// ---------------- fp32 weights [K,N] -> transposed fp8 planes [N,K] ---------
// h8 = e4m3(64*bf16hi(w)), l8 = e4m3(16384*(w - bf16hi(w)))
__global__ void __launch_bounds__(256) fp8w_kernel(
    const float* __restrict__ src, uint8_t* __restrict__ h8,
    uint8_t* __restrict__ l8, int K, int N)
{
    __shared__ float t[32][33];
    const int bx = blockIdx.x * 32;   // N offset
    const int by = blockIdx.y * 32;   // K offset
    const int x = threadIdx.x, ty = threadIdx.y;
#pragma unroll
    for (int yy = ty; yy < 32; yy += 8)
        t[yy][x] = src[(size_t)(by + yy) * N + bx + x];
    __syncthreads();
#pragma unroll
    for (int yy = ty; yy < 32; yy += 8) {
        const float v = t[x][yy];          // = src[(by+x)*N + bx+yy]
        const float hf = __bfloat162float(__float2bfloat16(v));
        const size_t o = (size_t)(bx + yy) * K + by + x;
        h8[o] = f2e4m3(64.0f * hf);
        l8[o] = f2e4m3(16384.0f * (v - hf));
    }
}

// ---------------- PTX helpers ----------------------------------------------
__device__ __forceinline__ void cpasync16(void* s, const void* g) {
    unsigned sa = (unsigned)__cvta_generic_to_shared(s);
    asm volatile("cp.async.cg.shared.global [%0], [%1], 16;\n" :: "r"(sa), "l"(g));
}
__device__ __forceinline__ void cp_commit() {
    asm volatile("cp.async.commit_group;\n" ::: "memory");
}
__device__ __forceinline__ void cp_wait0() {
    asm volatile("cp.async.wait_group 0;\n" ::: "memory");
}
__device__ __forceinline__ void cp_wait1() {
    asm volatile("cp.async.wait_group 1;\n" ::: "memory");
}
__device__ __forceinline__ void ldsm4(unsigned* r, const void* p) {
    unsigned a = (unsigned)__cvta_generic_to_shared(p);
    asm volatile("ldmatrix.sync.aligned.m8n8.x4.shared.b16 {%0,%1,%2,%3}, [%4];"
                 : "=r"(r[0]), "=r"(r[1]), "=r"(r[2]), "=r"(r[3]) : "r"(a));
}
__device__ __forceinline__ void ldsm4t(unsigned* r, const void* p) {
    unsigned a = (unsigned)__cvta_generic_to_shared(p);
    asm volatile("ldmatrix.sync.aligned.m8n8.x4.trans.shared.b16 {%0,%1,%2,%3}, [%4];"
                 : "=r"(r[0]), "=r"(r[1]), "=r"(r[2]), "=r"(r[3]) : "r"(a));
}
__device__ __forceinline__ void mma16816(float* d, const unsigned* a, const unsigned* b) {
    asm volatile("mma.sync.aligned.m16n8k16.row.col.f32.bf16.bf16.f32 "
                 "{%0,%1,%2,%3},{%4,%5,%6,%7},{%8,%9},{%0,%1,%2,%3};"
                 : "+f"(d[0]), "+f"(d[1]), "+f"(d[2]), "+f"(d[3])
                 : "r"(a[0]), "r"(a[1]), "r"(a[2]), "r"(a[3]), "r"(b[0]), "r"(b[1]));
}
// fp8 e4m3 mma, K=32 per instruction (2x MAC of bf16 k16)
__device__ __forceinline__ void mma16832q(float* d, const unsigned* a, const unsigned* b) {
    asm volatile("mma.sync.aligned.m16n8k32.row.col.f32.e4m3.e4m3.f32 "
                 "{%0,%1,%2,%3},{%4,%5,%6,%7},{%8,%9},{%0,%1,%2,%3};"
                 : "+f"(d[0]), "+f"(d[1]), "+f"(d[2]), "+f"(d[3])
                 : "r"(a[0]), "r"(a[1]), "r"(a[2]), "r"(a[3]), "r"(b[0]), "r"(b[1]));
}
__device__ __forceinline__ unsigned swz(unsigned o) { return o ^ ((o >> 3) & 0x70); }

__device__ __forceinline__ void f2bf_split(float x, float y, unsigned& hi, unsigned& lo) {
    __nv_bfloat162 h = __floats2bfloat162_rn(x, y);
    float rx = x - __bfloat162float(h.x);
    float ry = y - __bfloat162float(h.y);
    __nv_bfloat162 l = __floats2bfloat162_rn(rx, ry);
    hi = *(unsigned*)&h; lo = *(unsigned*)&l;
}

// ---------------- hybrid bf16-main + fp8-correction GEMM --------------------
// C = Ah*Bh (bf16 mma) + [Ah*Bl + Al*Bh] (e4m3 mma, scaled 2^16, merged at end)
// A row-major [M,K]; Bh [K,N] bf16; fp8 planes A8 [M,K], B8 [N,K].
// BM=128 BN=128 BK=32, 256 threads = 8 warps (2x4), warp tile 64x32.
#define OFF_AH  0            // 128 rows x 112 B (56 bf16)         = 14336
#define OFF_BH  14336        // 32 rows x 272 B (136 bf16)         =  8704
#define OFF_A8H 23040        // 128 rows x 48 B (32 fp8 + pad)     =  6144
#define OFF_A8L 29184
#define OFF_B8H 35328
#define OFF_B8L 41472
#define STAGE_BYTES 47616
#define GEMM_SMEM (3 * STAGE_BYTES)   // 142848 B

__global__ void __launch_bounds__(256, 1) gemm_hy(
    const __nv_bfloat16* __restrict__ Ah,
    const uint8_t* __restrict__ A8h, const uint8_t* __restrict__ A8l,
    const __nv_bfloat16* __restrict__ Bh,
    const uint8_t* __restrict__ B8h, const uint8_t* __restrict__ B8l,
    float* __restrict__ C, int M, int N, int K)
{
    extern __shared__ char sm[];
    const int tid  = threadIdx.x;
    const int warp = tid >> 5, lane = tid & 31;
    const int bm = blockIdx.y * 128, bn = blockIdx.x * 128;
    const int wm = (warp >> 2) * 64, wn = (warp & 3) * 32;

    float acc[4][4][4], corr[4][4][4];
#pragma unroll
    for (int i = 0; i < 4; i++)
#pragma unroll
        for (int j = 0; j < 4; j++)
#pragma unroll
            for (int d = 0; d < 4; d++) { acc[i][j][d] = 0.0f; corr[i][j][d] = 0.0f; }

    const int kIters = K >> 5;

#define LOAD_STAGE(s, k0) do {                                                  \
        char* S = sm + (s) * STAGE_BYTES;                                       \
        _Pragma("unroll")                                                       \
        for (int cc = 0; cc < 2; cc++) {                                        \
            const int c  = tid + cc * 256;                                      \
            const int ar = c >> 2, ac = c & 3;                                  \
            cpasync16(S + OFF_AH + ar * 112 + ac * 16,                          \
                      Ah + (size_t)(bm + ar) * K + (k0) + ac * 8);              \
            const int br = c >> 4, bc = c & 15;                                 \
            cpasync16(S + OFF_BH + br * 272 + bc * 16,                          \
                      Bh + (size_t)((k0) + br) * N + bn + bc * 8);              \
        }                                                                       \
        {                                                                       \
            const int r8 = tid >> 1, c8 = tid & 1;                              \
            cpasync16(S + OFF_A8H + r8 * 48 + c8 * 16,                          \
                      A8h + (size_t)(bm + r8) * K + (k0) + c8 * 16);            \
            cpasync16(S + OFF_A8L + r8 * 48 + c8 * 16,                          \
                      A8l + (size_t)(bm + r8) * K + (k0) + c8 * 16);            \
            cpasync16(S + OFF_B8H + r8 * 48 + c8 * 16,                          \
                      B8h + (size_t)(bn + r8) * K + (k0) + c8 * 16);            \
            cpasync16(S + OFF_B8L + r8 * 48 + c8 * 16,                          \
                      B8l + (size_t)(bn + r8) * K + (k0) + c8 * 16);            \
        }                                                                       \
        cp_commit();                                                            \
    } while (0)

    LOAD_STAGE(0, 0);
    LOAD_STAGE(1, 32);

    for (int it = 0; it < kIters; it++) {
        const int s = it % 3;
        if (it + 1 < kIters) cp_wait1(); else cp_wait0();
        __syncthreads();
        if (it + 2 < kIters) LOAD_STAGE((it + 2) % 3, (it + 2) * 32);

        char* S = sm + s * STAGE_BYTES;

        // ---- bf16 main product (2 x K16) ----
#pragma unroll
        for (int kk = 0; kk < 2; kk++) {
            unsigned ah[4][4];
#pragma unroll
            for (int i = 0; i < 4; i++)
                ldsm4(ah[i], S + OFF_AH + (wm + i * 16 + (lane & 15)) * 112
                              + kk * 32 + (lane >> 4) * 16);
            unsigned bh[4][2];
#pragma unroll
            for (int jj = 0; jj < 2; jj++) {
                unsigned t[4];
                ldsm4t(t, S + OFF_BH + (kk * 16 + (lane & 15)) * 272
                           + (wn + jj * 16 + (lane >> 4) * 8) * 2);
                bh[2 * jj][0] = t[0]; bh[2 * jj][1] = t[1];
                bh[2 * jj + 1][0] = t[2]; bh[2 * jj + 1][1] = t[3];
            }
#pragma unroll
            for (int i = 0; i < 4; i++)
#pragma unroll
                for (int j = 0; j < 4; j++)
                    mma16816(acc[i][j], ah[i], bh[j]);
        }

        // ---- fp8 corrections (K32 per mma) ----
        unsigned b8h_[2][4], b8l_[2][4];
#pragma unroll
        for (int u = 0; u < 2; u++) {
            ldsm4(b8h_[u], S + OFF_B8H + (wn + u * 16 + (lane & 15)) * 48 + (lane >> 4) * 16);
            ldsm4(b8l_[u], S + OFF_B8L + (wn + u * 16 + (lane & 15)) * 48 + (lane >> 4) * 16);
        }
#pragma unroll
        for (int i = 0; i < 4; i++) {
            unsigned a8h_[4], a8l_[4];
            ldsm4(a8h_, S + OFF_A8H + (wm + i * 16 + (lane & 15)) * 48 + (lane >> 4) * 16);
            ldsm4(a8l_, S + OFF_A8L + (wm + i * 16 + (lane & 15)) * 48 + (lane >> 4) * 16);
#pragma unroll
            for (int jj = 0; jj < 4; jj++) {
                const int u = jj >> 1, sl = jj & 1;
                unsigned bb[2];
                bb[0] = b8l_[u][sl]; bb[1] = b8l_[u][sl + 2];
                mma16832q(corr[i][jj], a8h_, bb);   // ah * bl
                bb[0] = b8h_[u][sl]; bb[1] = b8h_[u][sl + 2];
                mma16832q(corr[i][jj], a8l_, bb);   // al * bh
            }
        }
    }

    // merge corrections (scale 1/(4*64*256) = 2^-16) and store
#pragma unroll
    for (int i = 0; i < 4; i++)
#pragma unroll
        for (int j = 0; j < 4; j++) {
            const int r = bm + wm + i * 16 + (lane >> 2);
            const int c = bn + wn + j * 8 + (lane & 3) * 2;
            const float k = 1.0f / 65536.0f;
            float2 c0 = make_float2(fmaf(corr[i][j][0], k, acc[i][j][0]),
                                    fmaf(corr[i][j][1], k, acc[i][j][1]));
            float2 c1 = make_float2(fmaf(corr[i][j][2], k, acc[i][j][2]),
                                    fmaf(corr[i][j][3], k, acc[i][j][3]));
            *(float2*)(C + (size_t)r * N + c)       = c0;
            *(float2*)(C + (size_t)(r + 8) * N + c) = c1;
        }
}

// ---------------- fused RoPE + bf16 hi/lo split -----------------------------
__global__ void rope_split_kernel(
    const float* __restrict__ buf, __nv_bfloat16* __restrict__ hi,
    __nv_bfloat16* __restrict__ lo, int rowlen, int heads)
{
    const int idx = blockIdx.x * blockDim.x + threadIdx.x;
    const int total = MROWS * heads * 32;
    if (idx >= total) return;
    const int j  = idx & 31;
    const int t1 = idx >> 5;
    const int h  = t1 % heads;
    const int r  = t1 / heads;
    const float tn = (float)(r & (SEQ - 1));

    const size_t base = (size_t)r * rowlen + h * HDIM;
    const float x1 = buf[base + j];
    const float x2 = buf[base + j + 32];

    const float a1 = tn * g_freqs[j >> 1];
    const float a2 = tn * g_freqs[16 + (j >> 1)];
    float s1, c1, s2, c2;
    sincosf(a1, &s1, &c1);
    sincosf(a2, &s2, &c2);
    const float o1 = x1 * c1 - x2 * s1;
    const float o2 = x1 * s2 + x2 * c2;

    const __nv_bfloat16 h1 = __float2bfloat16(o1);
    const __nv_bfloat16 l1 = __float2bfloat16(o1 - __bfloat162float(h1));
    const __nv_bfloat16 h2 = __float2bfloat16(o2);
    const __nv_bfloat16 l2 = __float2bfloat16(o2 - __bfloat162float(h2));
    hi[base + j]      = h1;  lo[base + j]      = l1;
    hi[base + j + 32] = h2;  lo[base + j + 32] = l2;
}

// ---------------- Flash attention on tensor cores (split-bf16) -------------
#define FL_SMEM (6 * 8192 + 256)

__global__ void __launch_bounds__(128, 2) flash_mma_kernel(
    const __nv_bfloat16* __restrict__ Qh, const __nv_bfloat16* __restrict__ Ql,
    const __nv_bfloat16* __restrict__ Kh, const __nv_bfloat16* __restrict__ Kl,
    const __nv_bfloat16* __restrict__ Vh, const __nv_bfloat16* __restrict__ Vl,
    const int* __restrict__ mask,
    __nv_bfloat16* __restrict__ Oh, __nv_bfloat16* __restrict__ Ol)
{
    extern __shared__ char smc[];
    char* Qsh = smc;
    char* Qsl = smc + 8192;
    char* Ksh = smc + 16384;
    char* Ksl = smc + 24576;
    char* Vsh = smc + 32768;
    char* Vsl = smc + 40960;
    float* bias = (float*)(smc + 49152);

    const int qt = (gridDim.x - 1) - blockIdx.x;
    const int h = blockIdx.y, b = blockIdx.z;
    const int kvh = h >> 2;
    const int tid = threadIdx.x, warp = tid >> 5, lane = tid & 31;
    const int g = lane >> 2, t2 = (lane & 3) * 2;
    const float scale = 0.125f;
    const float slope = exp2f(-0.25f * (float)(h + 1));

    {
        const size_t base = (size_t)(b * SEQ + qt * 64) * 2048 + h * 64;
#pragma unroll
        for (int cc = 0; cc < 4; cc++) {
            const int c = tid + cc * 128;
            const int row = c >> 3, k8 = c & 7;
            const size_t gp = base + (size_t)row * 2048 + k8 * 8;
            const unsigned so = swz(row * 128 + k8 * 16);
            cpasync16(Qsh + so, Qh + gp);
            cpasync16(Qsl + so, Ql + gp);
        }
        cp_commit(); cp_wait0();
        __syncthreads();
    }
    unsigned qh[4][4], ql[4][4];
#pragma unroll
    for (int kc = 0; kc < 4; kc++) {
        const unsigned ad = swz((warp * 16 + (lane & 15)) * 128 + kc * 32 + (lane >> 4) * 16);
        ldsm4(qh[kc], Qsh + ad);
        ldsm4(ql[kc], Qsl + ad);
    }

    float o[8][4];
#pragma unroll
    for (int j = 0; j < 8; j++)
#pragma unroll
        for (int d = 0; d < 4; d++) o[j][d] = 0.0f;
    float m0 = -1e30f, m1 = -1e30f, l0 = 0.0f, l1 = 0.0f;
    const int qrow0 = qt * 64 + warp * 16 + g;

    for (int kt = 0; kt <= qt; kt++) {
        __syncthreads();
        {
            const size_t kbase = (size_t)(b * SEQ + kt * 64) * 512 + kvh * 64;
#pragma unroll
            for (int cc = 0; cc < 4; cc++) {
                const int c = tid + cc * 128;
                const int row = c >> 3, k8 = c & 7;
                const size_t gp = kbase + (size_t)row * 512 + k8 * 8;
                const unsigned so = swz(row * 128 + k8 * 16);
                cpasync16(Ksh + so, Kh + gp);
                cpasync16(Ksl + so, Kl + gp);
                cpasync16(Vsh + so, Vh + gp);
                cpasync16(Vsl + so, Vl + gp);
            }
        }
        if (tid < 64) bias[tid] = mask[b * SEQ + kt * 64 + tid] ? 0.0f : -1e30f;
        cp_commit(); cp_wait0();
        __syncthreads();

        float s[8][4];
#pragma unroll
        for (int j = 0; j < 8; j++)
#pragma unroll
            for (int d = 0; d < 4; d++) s[j][d] = 0.0f;

#pragma unroll
        for (int kc = 0; kc < 4; kc++) {
            unsigned kth[4][4], ktl[4][4];
#pragma unroll
            for (int jj = 0; jj < 4; jj++) {
                const unsigned ad = swz((jj * 16 + (lane & 15)) * 128 + kc * 32 + (lane >> 4) * 16);
                ldsm4(kth[jj], Ksh + ad);
                ldsm4(ktl[jj], Ksl + ad);
            }
#pragma unroll
            for (int jj = 0; jj < 4; jj++) {
                unsigned bfr[2];
                bfr[0] = kth[jj][0]; bfr[1] = kth[jj][2];
                mma16816(s[2 * jj], qh[kc], bfr);
                bfr[0] = kth[jj][1]; bfr[1] = kth[jj][3];
                mma16816(s[2 * jj + 1], qh[kc], bfr);
            }
#pragma unroll
            for (int jj = 0; jj < 4; jj++) {
                unsigned bfr[2];
                bfr[0] = kth[jj][0]; bfr[1] = kth[jj][2];
                mma16816(s[2 * jj], ql[kc], bfr);
                bfr[0] = kth[jj][1]; bfr[1] = kth[jj][3];
                mma16816(s[2 * jj + 1], ql[kc], bfr);
            }
#pragma unroll
            for (int jj = 0; jj < 4; jj++) {
                unsigned bfr[2];
                bfr[0] = ktl[jj][0]; bfr[1] = ktl[jj][2];
                mma16816(s[2 * jj], qh[kc], bfr);
                bfr[0] = ktl[jj][1]; bfr[1] = ktl[jj][3];
                mma16816(s[2 * jj + 1], qh[kc], bfr);
            }
        }

#pragma unroll
        for (int j = 0; j < 8; j++) {
            const int kg = kt * 64 + j * 8 + t2;
            const float b0 = bias[j * 8 + t2];
            const float b1 = bias[j * 8 + t2 + 1];
            const float al0 = fmaf(slope, (float)kg, b0);
            const float al1 = fmaf(slope, (float)(kg + 1), b1);
            float v0 = fmaf(s[j][0], scale, al0);
            float v1 = fmaf(s[j][1], scale, al1);
            float v2 = fmaf(s[j][2], scale, al0);
            float v3 = fmaf(s[j][3], scale, al1);
            if (kg     > qrow0)     v0 = -1e30f;
            if (kg + 1 > qrow0)     v1 = -1e30f;
            if (kg     > qrow0 + 8) v2 = -1e30f;
            if (kg + 1 > qrow0 + 8) v3 = -1e30f;
            s[j][0] = v0; s[j][1] = v1; s[j][2] = v2; s[j][3] = v3;
        }

        float mx0 = -1e30f, mx1 = -1e30f;
#pragma unroll
        for (int j = 0; j < 8; j++) {
            mx0 = fmaxf(mx0, fmaxf(s[j][0], s[j][1]));
            mx1 = fmaxf(mx1, fmaxf(s[j][2], s[j][3]));
        }
        mx0 = fmaxf(mx0, __shfl_xor_sync(0xffffffffu, mx0, 1));
        mx0 = fmaxf(mx0, __shfl_xor_sync(0xffffffffu, mx0, 2));
        mx1 = fmaxf(mx1, __shfl_xor_sync(0xffffffffu, mx1, 1));
        mx1 = fmaxf(mx1, __shfl_xor_sync(0xffffffffu, mx1, 2));
        const float mn0 = fmaxf(m0, mx0), mn1 = fmaxf(m1, mx1);
        const float cr0 = __expf(m0 - mn0), cr1 = __expf(m1 - mn1);
        float ps0 = 0.0f, ps1 = 0.0f;
#pragma unroll
        for (int j = 0; j < 8; j++) {
            s[j][0] = __expf(s[j][0] - mn0);
            s[j][1] = __expf(s[j][1] - mn0);
            s[j][2] = __expf(s[j][2] - mn1);
            s[j][3] = __expf(s[j][3] - mn1);
            ps0 += s[j][0] + s[j][1];
            ps1 += s[j][2] + s[j][3];
        }
        ps0 += __shfl_xor_sync(0xffffffffu, ps0, 1);
        ps0 += __shfl_xor_sync(0xffffffffu, ps0, 2);
        ps1 += __shfl_xor_sync(0xffffffffu, ps1, 1);
        ps1 += __shfl_xor_sync(0xffffffffu, ps1, 2);
        l0 = l0 * cr0 + ps0; m0 = mn0;
        l1 = l1 * cr1 + ps1; m1 = mn1;
#pragma unroll
        for (int j = 0; j < 8; j++) {
            o[j][0] *= cr0; o[j][1] *= cr0;
            o[j][2] *= cr1; o[j][3] *= cr1;
        }

#pragma unroll
        for (int kc = 0; kc < 4; kc++) {
            unsigned ph[4], pl[4];
            f2bf_split(s[2 * kc][0],     s[2 * kc][1],     ph[0], pl[0]);
            f2bf_split(s[2 * kc][2],     s[2 * kc][3],     ph[1], pl[1]);
            f2bf_split(s[2 * kc + 1][0], s[2 * kc + 1][1], ph[2], pl[2]);
            f2bf_split(s[2 * kc + 1][2], s[2 * kc + 1][3], ph[3], pl[3]);
            unsigned vth[4][4], vtl[4][4];
#pragma unroll
            for (int jj = 0; jj < 4; jj++) {
                const unsigned ad = swz((kc * 16 + (lane & 15)) * 128 + jj * 32 + (lane >> 4) * 16);
                ldsm4t(vth[jj], Vsh + ad);
                ldsm4t(vtl[jj], Vsl + ad);
            }
#pragma unroll
            for (int jj = 0; jj < 4; jj++) {
                unsigned bfr[2];
                bfr[0] = vth[jj][0]; bfr[1] = vth[jj][1];
                mma16816(o[2 * jj], ph, bfr);
                bfr[0] = vth[jj][2]; bfr[1] = vth[jj][3];
                mma16816(o[2 * jj + 1], ph, bfr);
            }
#pragma unroll
            for (int jj = 0; jj < 4; jj++) {
                unsigned bfr[2];
                bfr[0] = vth[jj][0]; bfr[1] = vth[jj][1];
                mma16816(o[2 * jj], pl, bfr);
                bfr[0] = vth[jj][2]; bfr[1] = vth[jj][3];
                mma16816(o[2 * jj + 1], pl, bfr);
            }
#pragma unroll
            for (int jj = 0; jj < 4; jj++) {
                unsigned bfr[2];
                bfr[0] = vtl[jj][0]; bfr[1] = vtl[jj][1];
                mma16816(o[2 * jj], ph, bfr);
                bfr[0] = vtl[jj][2]; bfr[1] = vtl[jj][3];
                mma16816(o[2 * jj + 1], ph, bfr);
            }
        }
    }

    const float inv0 = 1.0f / l0, inv1 = 1.0f / l1;
#pragma unroll
    for (int j = 0; j < 8; j++) {
        const size_t p0 = (size_t)(b * SEQ + qrow0) * 2048 + h * 64 + j * 8 + t2;
        unsigned hh, ll;
        f2bf_split(o[j][0] * inv0, o[j][1] * inv0, hh, ll);
        *(unsigned*)(Oh + p0) = hh;
        *(unsigned*)(Ol + p0) = ll;
        f2bf_split(o[j][2] * inv1, o[j][3] * inv1, hh, ll);
        *(unsigned*)(Oh + p0 + 8 * 2048) = hh;
        *(unsigned*)(Ol + p0 + 8 * 2048) = ll;
    }
}

// ---------------- host launcher -------------------------------------------
extern "C" void kernel_launch(void* const* d_in, const int* in_sizes, int n_in,
                              void* d_out, int out_size)
{
    const float* x    = (const float*)d_in[0];
    const int*   mask = (const int*)  d_in[1];
    const float* Wq   = (const float*)d_in[2];
    const float* Wk   = (const float*)d_in[3];
    const float* Wv   = (const float*)d_in[4];
    const float* Wo   = (const float*)d_in[5];
    float* out = (float*)d_out;

    void *pQ, *pK, *pV;
    void *pxh, *pxl, *pWqh, *pWql, *pWkh, *pWkl, *pWvh, *pWvl, *pWoh, *pWol;
    void *pQh, *pQl, *pKh, *pKl, *pVh, *pVl, *pOh, *pOl;
    void *px8h, *px8l, *pWq8h, *pWq8l, *pWk8h, *pWk8l, *pWv8h, *pWv8l, *pWo8h, *pWo8l, *pO8h, *pO8l;
    cudaGetSymbolAddress(&pQ, g_Q);  cudaGetSymbolAddress(&pK, g_K);
    cudaGetSymbolAddress(&pV, g_V);
    cudaGetSymbolAddress(&pxh, g_xh);  cudaGetSymbolAddress(&pxl, g_xl);
    cudaGetSymbolAddress(&pWqh, g_Wqh); cudaGetSymbolAddress(&pWql, g_Wql);
    cudaGetSymbolAddress(&pWkh, g_Wkh); cudaGetSymbolAddress(&pWkl, g_Wkl);
    cudaGetSymbolAddress(&pWvh, g_Wvh); cudaGetSymbolAddress(&pWvl, g_Wvl);
    cudaGetSymbolAddress(&pWoh, g_Woh); cudaGetSymbolAddress(&pWol, g_Wol);
    cudaGetSymbolAddress(&pQh, g_Qh);   cudaGetSymbolAddress(&pQl, g_Ql);
    cudaGetSymbolAddress(&pKh, g_Kh);   cudaGetSymbolAddress(&pKl, g_Kl);
    cudaGetSymbolAddress(&pVh, g_Vh);   cudaGetSymbolAddress(&pVl, g_Vl);
    cudaGetSymbolAddress(&pOh, g_Oh);   cudaGetSymbolAddress(&pOl, g_Ol);
    cudaGetSymbolAddress(&px8h, g_x8h);   cudaGetSymbolAddress(&px8l, g_x8l);
    cudaGetSymbolAddress(&pWq8h, g_Wq8h); cudaGetSymbolAddress(&pWq8l, g_Wq8l);
    cudaGetSymbolAddress(&pWk8h, g_Wk8h); cudaGetSymbolAddress(&pWk8l, g_Wk8l);
    cudaGetSymbolAddress(&pWv8h, g_Wv8h); cudaGetSymbolAddress(&pWv8l, g_Wv8l);
    cudaGetSymbolAddress(&pWo8h, g_Wo8h); cudaGetSymbolAddress(&pWo8l, g_Wo8l);
    cudaGetSymbolAddress(&pO8h, g_O8h);   cudaGetSymbolAddress(&pO8l, g_O8l);

    init_freqs_kernel<<<1, 32>>>();

    // bf16 hi planes (main product) + fp8 planes (corrections)
    split_kernel<<<(MROWS * DMODEL / 4) / 256, 256>>>(x,  (__nv_bfloat16*)pxh, (__nv_bfloat16*)pxl, MROWS * DMODEL / 4);
    split_kernel<<<(DMODEL * 2048 / 4) / 256, 256>>>(Wq, (__nv_bfloat16*)pWqh, (__nv_bfloat16*)pWql, DMODEL * 2048 / 4);
    split_kernel<<<(DMODEL * 512  / 4) / 256, 256>>>(Wk, (__nv_bfloat16*)pWkh, (__nv_bfloat16*)pWkl, DMODEL * 512 / 4);
    split_kernel<<<(DMODEL * 512  / 4) / 256, 256>>>(Wv, (__nv_bfloat16*)pWvh, (__nv_bfloat16*)pWvl, DMODEL * 512 / 4);
    split_kernel<<<(2048 * DMODEL / 4) / 256, 256>>>(Wo, (__nv_bfloat16*)pWoh, (__nv_bfloat16*)pWol, 2048 * DMODEL / 4);

    fp8a_kernel<<<(MROWS * DMODEL / 4) / 256, 256>>>(x, (uint8_t*)px8h, (uint8_t*)px8l, MROWS * DMODEL / 4);
    fp8w_kernel<<<dim3(2048 / 32, DMODEL / 32), dim3(32, 8)>>>(Wq, (uint8_t*)pWq8h, (uint8_t*)pWq8l, DMODEL, 2048);
    fp8w_kernel<<<dim3(512  / 32, DMODEL / 32), dim3(32, 8)>>>(Wk, (uint8_t*)pWk8h, (uint8_t*)pWk8l, DMODEL, 512);
    fp8w_kernel<<<dim3(512  / 32, DMODEL / 32), dim3(32, 8)>>>(Wv, (uint8_t*)pWv8h, (uint8_t*)pWv8l, DMODEL, 512);
    fp8w_kernel<<<dim3(2048 / 32, 2048 / 32),   dim3(32, 8)>>>(Wo, (uint8_t*)pWo8h, (uint8_t*)pWo8l, 2048, 2048);

    cudaFuncSetAttribute(gemm_hy, cudaFuncAttributeMaxDynamicSharedMemorySize, GEMM_SMEM);

    // QKV projections (hybrid bf16 + fp8)
    gemm_hy<<<dim3(2048 / 128, MROWS / 128), 256, GEMM_SMEM>>>(
        (const __nv_bfloat16*)pxh, (const uint8_t*)px8h, (const uint8_t*)px8l,
        (const __nv_bfloat16*)pWqh, (const uint8_t*)pWq8h, (const uint8_t*)pWq8l,
        (float*)pQ, MROWS, 2048, DMODEL);
    gemm_hy<<<dim3(512 / 128, MROWS / 128), 256, GEMM_SMEM>>>(
        (const __nv_bfloat16*)pxh, (const uint8_t*)px8h, (const uint8_t*)px8l,
        (const __nv_bfloat16*)pWkh, (const uint8_t*)pWk8h, (const uint8_t*)pWk8l,
        (float*)pK, MROWS, 512, DMODEL);
    gemm_hy<<<dim3(512 / 128, MROWS / 128), 256, GEMM_SMEM>>>(
        (const __nv_bfloat16*)pxh, (const uint8_t*)px8h, (const uint8_t*)px8l,
        (const __nv_bfloat16*)pWvh, (const uint8_t*)pWv8h, (const uint8_t*)pWv8l,
        (float*)pV, MROWS, 512, DMODEL);

    // fused RoPE + split for Q and K; plain split for V
    rope_split_kernel<<<(MROWS * NHEADS  * 32) / 256, 256>>>(
        (const float*)pQ, (__nv_bfloat16*)pQh, (__nv_bfloat16*)pQl, NHEADS * HDIM, NHEADS);
    rope_split_kernel<<<(MROWS * KVHEADS * 32) / 256, 256>>>(
        (const float*)pK, (__nv_bfloat16*)pKh, (__nv_bfloat16*)pKl, KVHEADS * HDIM, KVHEADS);
    split_kernel<<<(MROWS * 512 / 4) / 256, 256>>>(
        (const float*)pV, (__nv_bfloat16*)pVh, (__nv_bfloat16*)pVl, MROWS * 512 / 4);

    // Flash attention (tensor cores, split-bf16)
    cudaFuncSetAttribute(flash_mma_kernel, cudaFuncAttributeMaxDynamicSharedMemorySize, FL_SMEM);
    flash_mma_kernel<<<dim3(SEQ / 64, NHEADS, BATCH), 128, FL_SMEM>>>(
        (const __nv_bfloat16*)pQh, (const __nv_bfloat16*)pQl,
        (const __nv_bfloat16*)pKh, (const __nv_bfloat16*)pKl,
        (const __nv_bfloat16*)pVh, (const __nv_bfloat16*)pVl,
        mask, (__nv_bfloat16*)pOh, (__nv_bfloat16*)pOl);

    // O fp8 planes, then output projection (hybrid)
    fp8o_kernel<<<(MROWS * 2048 / 4) / 256, 256>>>(
        (const __nv_bfloat16*)pOh, (const __nv_bfloat16*)pOl,
        (uint8_t*)pO8h, (uint8_t*)pO8l, MROWS * 2048 / 4);
    gemm_hy<<<dim3(2048 / 128, MROWS / 128), 256, GEMM_SMEM>>>(
        (const __nv_bfloat16*)pOh, (const uint8_t*)pO8h, (const uint8_t*)pO8l,
        (const __nv_bfloat16*)pWoh, (const uint8_t*)pWo8h, (const uint8_t*)pWo8l,
        out, MROWS, 2048, DMODEL);
}

// round 13
// speedup vs baseline: 1.4809x; 1.4809x over previous
#include <cuda_runtime.h>
#include <cuda_bf16.h>
#include <cuda_fp16.h>
#include <math.h>
#include <stdint.h>

#define BATCH   2
#define SEQ     2048
#define DMODEL  2048
#define NHEADS  32
#define HDIM    64
#define KVHEADS 8
#define MROWS   (BATCH*SEQ)          // 4096

// ---------------- scratch (device globals; no allocation allowed) ----------
__device__ float g_Q[MROWS * NHEADS * HDIM];
__device__ float g_K[MROWS * KVHEADS * HDIM];
__device__ float g_V[MROWS * KVHEADS * HDIM];
__device__ float g_freqs[32];

// f16 planes for GEMMs (A-side single plane; weights hi+lo)
__device__ __half g_x16 [MROWS * DMODEL];
__device__ __half g_Wq16h[DMODEL * 2048];
__device__ __half g_Wq16l[DMODEL * 2048];
__device__ __half g_Wk16h[DMODEL * 512];
__device__ __half g_Wk16l[DMODEL * 512];
__device__ __half g_Wv16h[DMODEL * 512];
__device__ __half g_Wv16l[DMODEL * 512];
__device__ __half g_Wo16h[2048 * DMODEL];
__device__ __half g_Wo16l[2048 * DMODEL];
__device__ __half g_O16 [MROWS * 2048];

// bf16 hi/lo planes for flash (proven 3-product path)
__device__ __nv_bfloat16 g_Qh [MROWS * 2048];
__device__ __nv_bfloat16 g_Ql [MROWS * 2048];
__device__ __nv_bfloat16 g_Kh [MROWS * 512];
__device__ __nv_bfloat16 g_Kl [MROWS * 512];
__device__ __nv_bfloat16 g_Vh [MROWS * 512];
__device__ __nv_bfloat16 g_Vl [MROWS * 512];

// ---------------- RoPE frequency table -------------------------------------
__global__ void init_freqs_kernel() {
    int i = threadIdx.x;
    g_freqs[i] = (float)exp2(-(double)i * (13.287712379549449 / 32.0));
}

// ---------------- fp32 -> f16 single plane ----------------------------------
__global__ void __launch_bounds__(256) split16_kernel(
    const float* __restrict__ src, __half* __restrict__ dst, int n4)
{
    const int i = blockIdx.x * blockDim.x + threadIdx.x;
    if (i >= n4) return;
    const float4 f = ((const float4*)src)[i];
    __half2 a = __floats2half2_rn(f.x, f.y);
    __half2 b = __floats2half2_rn(f.z, f.w);
    uint2 v; v.x = *(unsigned*)&a; v.y = *(unsigned*)&b;
    *(uint2*)(dst + 4 * (size_t)i) = v;
}

// ---------------- fp32 weights -> f16 (hi, lo) planes -----------------------
__global__ void __launch_bounds__(256) wsplit16_kernel(
    const float* __restrict__ src, __half* __restrict__ hi,
    __half* __restrict__ lo, int n4)
{
    const int i = blockIdx.x * blockDim.x + threadIdx.x;
    if (i >= n4) return;
    const float4 f = ((const float4*)src)[i];
    const float fv[4] = {f.x, f.y, f.z, f.w};
    __half h[4], l[4];
#pragma unroll
    for (int k = 0; k < 4; k++) {
        h[k] = __float2half_rn(fv[k]);
        l[k] = __float2half_rn(fv[k] - __half2float(h[k]));
    }
    *(uint2*)(hi + 4 * (size_t)i) = *(uint2*)h;
    *(uint2*)(lo + 4 * (size_t)i) = *(uint2*)l;
}

// ---------------- fp32 -> (hi, lo) bf16 split (flash operands) --------------
__global__ void __launch_bounds__(256) split_kernel(
    const float* __restrict__ src, __nv_bfloat16* __restrict__ hi,
    __nv_bfloat16* __restrict__ lo, int n4)
{
    const int i = blockIdx.x * blockDim.x + threadIdx.x;
    if (i >= n4) return;
    const float4 f = ((const float4*)src)[i];
    __nv_bfloat16 h[4], l[4];
    const float fv[4] = {f.x, f.y, f.z, f.w};
#pragma unroll
    for (int k = 0; k < 4; k++) {
        h[k] = __float2bfloat16(fv[k]);
        l[k] = __float2bfloat16(fv[k] - __bfloat162float(h[k]));
    }
    *(uint2*)(hi + 4 * (size_t)i) = *(uint2*)h;
    *(uint2*)(lo + 4 * (size_t)i) = *(uint2*)l;
}

// ---------------- PTX helpers ----------------------------------------------
__device__ __forceinline__ void cpasync16(void* s, const void* g) {
    unsigned sa = (unsigned)__cvta_generic_to_shared(s);
    asm volatile("cp.async.cg.shared.global [%0], [%1], 16;\n" :: "r"(sa), "l"(g));
}
__device__ __forceinline__ void cp_commit() {
    asm volatile("cp.async.commit_group;\n" ::: "memory");
}
__device__ __forceinline__ void cp_wait0() {
    asm volatile("cp.async.wait_group 0;\n" ::: "memory");
}
__device__ __forceinline__ void cp_wait1() {
    asm volatile("cp.async.wait_group 1;\n" ::: "memory");
}
__device__ __forceinline__ void ldsm4(unsigned* r, const void* p) {
    unsigned a = (unsigned)__cvta_generic_to_shared(p);
    asm volatile("ldmatrix.sync.aligned.m8n8.x4.shared.b16 {%0,%1,%2,%3}, [%4];"
                 : "=r"(r[0]), "=r"(r[1]), "=r"(r[2]), "=r"(r[3]) : "r"(a));
}
__device__ __forceinline__ void ldsm4t(unsigned* r, const void* p) {
    unsigned a = (unsigned)__cvta_generic_to_shared(p);
    asm volatile("ldmatrix.sync.aligned.m8n8.x4.trans.shared.b16 {%0,%1,%2,%3}, [%4];"
                 : "=r"(r[0]), "=r"(r[1]), "=r"(r[2]), "=r"(r[3]) : "r"(a));
}
__device__ __forceinline__ void mma16816(float* d, const unsigned* a, const unsigned* b) {
    asm volatile("mma.sync.aligned.m16n8k16.row.col.f32.bf16.bf16.f32 "
                 "{%0,%1,%2,%3},{%4,%5,%6,%7},{%8,%9},{%0,%1,%2,%3};"
                 : "+f"(d[0]), "+f"(d[1]), "+f"(d[2]), "+f"(d[3])
                 : "r"(a[0]), "r"(a[1]), "r"(a[2]), "r"(a[3]), "r"(b[0]), "r"(b[1]));
}
__device__ __forceinline__ void mma16816h(float* d, const unsigned* a, const unsigned* b) {
    asm volatile("mma.sync.aligned.m16n8k16.row.col.f32.f16.f16.f32 "
                 "{%0,%1,%2,%3},{%4,%5,%6,%7},{%8,%9},{%0,%1,%2,%3};"
                 : "+f"(d[0]), "+f"(d[1]), "+f"(d[2]), "+f"(d[3])
                 : "r"(a[0]), "r"(a[1]), "r"(a[2]), "r"(a[3]), "r"(b[0]), "r"(b[1]));
}
__device__ __forceinline__ unsigned swz(unsigned o) { return o ^ ((o >> 3) & 0x70); }

__device__ __forceinline__ void f2bf_split(float x, float y, unsigned& hi, unsigned& lo) {
    __nv_bfloat162 h = __floats2bfloat162_rn(x, y);
    float rx = x - __bfloat162float(h.x);
    float ry = y - __bfloat162float(h.y);
    __nv_bfloat162 l = __floats2bfloat162_rn(rx, ry);
    hi = *(unsigned*)&h; lo = *(unsigned*)&l;
}

// ---------------- f16 2-product GEMM ----------------------------------------
// C = Ah*Bh + Ah*Bl, f32 accum. Ah = f16(A) [M,K]; Bh = f16(B), Bl = f16(B-Bh),
// both [K,N]. Dropped Al*Bh term ~2^-12 RMS. BM=128 BN=128 BK=32, 256 thr.
#define SA_STRIDE 56
#define SB_STRIDE 136
#define SA_PLANE  (128 * SA_STRIDE)   // 7168 elems
#define SB_PLANE  (32 * SB_STRIDE)    // 4352 elems
#define STAGE_ELEMS (SA_PLANE + 2 * SB_PLANE)   // 15872 elems = 31744 B
#define GEMM_SMEM (3 * STAGE_ELEMS * 2)         // 95232 B (3 stages)

__global__ void __launch_bounds__(256, 1) gemm_f16x2(
    const __half* __restrict__ Ah,
    const __half* __restrict__ Bh, const __half* __restrict__ Bl,
    float* __restrict__ C, int M, int N, int K)
{
    extern __shared__ __half sm[];
    const int tid  = threadIdx.x;
    const int warp = tid >> 5, lane = tid & 31;
    const int bm = blockIdx.y * 128, bn = blockIdx.x * 128;
    const int wm = (warp >> 2) * 64, wn = (warp & 3) * 32;

    float acc[4][4][4];
#pragma unroll
    for (int i = 0; i < 4; i++)
#pragma unroll
        for (int j = 0; j < 4; j++)
#pragma unroll
            for (int d = 0; d < 4; d++) acc[i][j][d] = 0.0f;

    const int kIters = K >> 5;

#define LOAD_STAGE(s, k0) do {                                                  \
        __half* Sah = sm + (s) * STAGE_ELEMS;                                   \
        __half* Sbh = Sah + SA_PLANE;                                           \
        __half* Sbl = Sbh + SB_PLANE;                                           \
        _Pragma("unroll")                                                       \
        for (int cc = 0; cc < 2; cc++) {                                        \
            const int c  = tid + cc * 256;                                      \
            const int ar = c >> 2, ac = c & 3;                                  \
            cpasync16(Sah + ar * SA_STRIDE + ac * 8,                            \
                      Ah + (size_t)(bm + ar) * K + (k0) + ac * 8);              \
            const int br = c >> 4, bc = c & 15;                                 \
            const size_t gb = (size_t)((k0) + br) * N + bn + bc * 8;            \
            cpasync16(Sbh + br * SB_STRIDE + bc * 8, Bh + gb);                  \
            cpasync16(Sbl + br * SB_STRIDE + bc * 8, Bl + gb);                  \
        }                                                                       \
        cp_commit();                                                            \
    } while (0)

    LOAD_STAGE(0, 0);
    LOAD_STAGE(1, 32);

    for (int it = 0; it < kIters; it++) {
        const int s = it % 3;
        if (it + 1 < kIters) cp_wait1(); else cp_wait0();
        __syncthreads();
        if (it + 2 < kIters) LOAD_STAGE((it + 2) % 3, (it + 2) * 32);

        const __half* Sah = sm + s * STAGE_ELEMS;
        const __half* Sbh = Sah + SA_PLANE;
        const __half* Sbl = Sbh + SB_PLANE;

#pragma unroll
        for (int kk = 0; kk < 2; kk++) {
            unsigned ah[4][4];
#pragma unroll
            for (int i = 0; i < 4; i++)
                ldsm4(ah[i], Sah + (wm + i * 16 + (lane & 15)) * SA_STRIDE
                              + kk * 16 + (lane >> 4) * 8);
            unsigned bh[4][2], bl[4][2];
#pragma unroll
            for (int jj = 0; jj < 2; jj++) {
                const int off = (kk * 16 + (lane & 15)) * SB_STRIDE
                              + wn + jj * 16 + (lane >> 4) * 8;
                unsigned t[4];
                ldsm4t(t, Sbh + off);
                bh[2 * jj][0] = t[0]; bh[2 * jj][1] = t[1];
                bh[2 * jj + 1][0] = t[2]; bh[2 * jj + 1][1] = t[3];
                ldsm4t(t, Sbl + off);
                bl[2 * jj][0] = t[0]; bl[2 * jj][1] = t[1];
                bl[2 * jj + 1][0] = t[2]; bl[2 * jj + 1][1] = t[3];
            }
#pragma unroll
            for (int i = 0; i < 4; i++)
#pragma unroll
                for (int j = 0; j < 4; j++)
                    mma16816h(acc[i][j], ah[i], bh[j]);
#pragma unroll
            for (int i = 0; i < 4; i++)
#pragma unroll
                for (int j = 0; j < 4; j++)
                    mma16816h(acc[i][j], ah[i], bl[j]);
        }
    }

    // epilogue
#pragma unroll
    for (int i = 0; i < 4; i++)
#pragma unroll
        for (int j = 0; j < 4; j++) {
            const int r = bm + wm + i * 16 + (lane >> 2);
            const int c = bn + wn + j * 8 + (lane & 3) * 2;
            *(float2*)(C + (size_t)r * N + c)       = make_float2(acc[i][j][0], acc[i][j][1]);
            *(float2*)(C + (size_t)(r + 8) * N + c) = make_float2(acc[i][j][2], acc[i][j][3]);
        }
}

// ---------------- fused RoPE + bf16 hi/lo split -----------------------------
__global__ void rope_split_kernel(
    const float* __restrict__ buf, __nv_bfloat16* __restrict__ hi,
    __nv_bfloat16* __restrict__ lo, int rowlen, int heads)
{
    const int idx = blockIdx.x * blockDim.x + threadIdx.x;
    const int total = MROWS * heads * 32;
    if (idx >= total) return;
    const int j  = idx & 31;
    const int t1 = idx >> 5;
    const int h  = t1 % heads;
    const int r  = t1 / heads;
    const float tn = (float)(r & (SEQ - 1));

    const size_t base = (size_t)r * rowlen + h * HDIM;
    const float x1 = buf[base + j];
    const float x2 = buf[base + j + 32];

    const float a1 = tn * g_freqs[j >> 1];
    const float a2 = tn * g_freqs[16 + (j >> 1)];
    float s1, c1, s2, c2;
    sincosf(a1, &s1, &c1);
    sincosf(a2, &s2, &c2);
    const float o1 = x1 * c1 - x2 * s1;
    const float o2 = x1 * s2 + x2 * c2;

    const __nv_bfloat16 h1 = __float2bfloat16(o1);
    const __nv_bfloat16 l1 = __float2bfloat16(o1 - __bfloat162float(h1));
    const __nv_bfloat16 h2 = __float2bfloat16(o2);
    const __nv_bfloat16 l2 = __float2bfloat16(o2 - __bfloat162float(h2));
    hi[base + j]      = h1;  lo[base + j]      = l1;
    hi[base + j + 32] = h2;  lo[base + j + 32] = l2;
}

// ---------------- Flash attention on tensor cores (split-bf16) -------------
#define FL_SMEM (6 * 8192 + 256)

__global__ void __launch_bounds__(128, 2) flash_mma_kernel(
    const __nv_bfloat16* __restrict__ Qh, const __nv_bfloat16* __restrict__ Ql,
    const __nv_bfloat16* __restrict__ Kh, const __nv_bfloat16* __restrict__ Kl,
    const __nv_bfloat16* __restrict__ Vh, const __nv_bfloat16* __restrict__ Vl,
    const int* __restrict__ mask,
    __half* __restrict__ O16)
{
    extern __shared__ char smc[];
    char* Qsh = smc;
    char* Qsl = smc + 8192;
    char* Ksh = smc + 16384;
    char* Ksl = smc + 24576;
    char* Vsh = smc + 32768;
    char* Vsl = smc + 40960;
    float* bias = (float*)(smc + 49152);

    const int qt = (gridDim.x - 1) - blockIdx.x;
    const int h = blockIdx.y, b = blockIdx.z;
    const int kvh = h >> 2;
    const int tid = threadIdx.x, warp = tid >> 5, lane = tid & 31;
    const int g = lane >> 2, t2 = (lane & 3) * 2;
    const float scale = 0.125f;
    const float slope = exp2f(-0.25f * (float)(h + 1));

    {
        const size_t base = (size_t)(b * SEQ + qt * 64) * 2048 + h * 64;
#pragma unroll
        for (int cc = 0; cc < 4; cc++) {
            const int c = tid + cc * 128;
            const int row = c >> 3, k8 = c & 7;
            const size_t gp = base + (size_t)row * 2048 + k8 * 8;
            const unsigned so = swz(row * 128 + k8 * 16);
            cpasync16(Qsh + so, Qh + gp);
            cpasync16(Qsl + so, Ql + gp);
        }
        cp_commit(); cp_wait0();
        __syncthreads();
    }
    unsigned qh[4][4], ql[4][4];
#pragma unroll
    for (int kc = 0; kc < 4; kc++) {
        const unsigned ad = swz((warp * 16 + (lane & 15)) * 128 + kc * 32 + (lane >> 4) * 16);
        ldsm4(qh[kc], Qsh + ad);
        ldsm4(ql[kc], Qsl + ad);
    }

    float o[8][4];
#pragma unroll
    for (int j = 0; j < 8; j++)
#pragma unroll
        for (int d = 0; d < 4; d++) o[j][d] = 0.0f;
    float m0 = -1e30f, m1 = -1e30f, l0 = 0.0f, l1 = 0.0f;
    const int qrow0 = qt * 64 + warp * 16 + g;

    for (int kt = 0; kt <= qt; kt++) {
        __syncthreads();
        {
            const size_t kbase = (size_t)(b * SEQ + kt * 64) * 512 + kvh * 64;
#pragma unroll
            for (int cc = 0; cc < 4; cc++) {
                const int c = tid + cc * 128;
                const int row = c >> 3, k8 = c & 7;
                const size_t gp = kbase + (size_t)row * 512 + k8 * 8;
                const unsigned so = swz(row * 128 + k8 * 16);
                cpasync16(Ksh + so, Kh + gp);
                cpasync16(Ksl + so, Kl + gp);
                cpasync16(Vsh + so, Vh + gp);
                cpasync16(Vsl + so, Vl + gp);
            }
        }
        if (tid < 64) bias[tid] = mask[b * SEQ + kt * 64 + tid] ? 0.0f : -1e30f;
        cp_commit(); cp_wait0();
        __syncthreads();

        float s[8][4];
#pragma unroll
        for (int j = 0; j < 8; j++)
#pragma unroll
            for (int d = 0; d < 4; d++) s[j][d] = 0.0f;

#pragma unroll
        for (int kc = 0; kc < 4; kc++) {
            unsigned kth[4][4], ktl[4][4];
#pragma unroll
            for (int jj = 0; jj < 4; jj++) {
                const unsigned ad = swz((jj * 16 + (lane & 15)) * 128 + kc * 32 + (lane >> 4) * 16);
                ldsm4(kth[jj], Ksh + ad);
                ldsm4(ktl[jj], Ksl + ad);
            }
#pragma unroll
            for (int jj = 0; jj < 4; jj++) {
                unsigned bfr[2];
                bfr[0] = kth[jj][0]; bfr[1] = kth[jj][2];
                mma16816(s[2 * jj], qh[kc], bfr);
                bfr[0] = kth[jj][1]; bfr[1] = kth[jj][3];
                mma16816(s[2 * jj + 1], qh[kc], bfr);
            }
#pragma unroll
            for (int jj = 0; jj < 4; jj++) {
                unsigned bfr[2];
                bfr[0] = kth[jj][0]; bfr[1] = kth[jj][2];
                mma16816(s[2 * jj], ql[kc], bfr);
                bfr[0] = kth[jj][1]; bfr[1] = kth[jj][3];
                mma16816(s[2 * jj + 1], ql[kc], bfr);
            }
#pragma unroll
            for (int jj = 0; jj < 4; jj++) {
                unsigned bfr[2];
                bfr[0] = ktl[jj][0]; bfr[1] = ktl[jj][2];
                mma16816(s[2 * jj], qh[kc], bfr);
                bfr[0] = ktl[jj][1]; bfr[1] = ktl[jj][3];
                mma16816(s[2 * jj + 1], qh[kc], bfr);
            }
        }

#pragma unroll
        for (int j = 0; j < 8; j++) {
            const int kg = kt * 64 + j * 8 + t2;
            const float b0 = bias[j * 8 + t2];
            const float b1 = bias[j * 8 + t2 + 1];
            const float al0 = fmaf(slope, (float)kg, b0);
            const float al1 = fmaf(slope, (float)(kg + 1), b1);
            float v0 = fmaf(s[j][0], scale, al0);
            float v1 = fmaf(s[j][1], scale, al1);
            float v2 = fmaf(s[j][2], scale, al0);
            float v3 = fmaf(s[j][3], scale, al1);
            if (kg     > qrow0)     v0 = -1e30f;
            if (kg + 1 > qrow0)     v1 = -1e30f;
            if (kg     > qrow0 + 8) v2 = -1e30f;
            if (kg + 1 > qrow0 + 8) v3 = -1e30f;
            s[j][0] = v0; s[j][1] = v1; s[j][2] = v2; s[j][3] = v3;
        }

        float mx0 = -1e30f, mx1 = -1e30f;
#pragma unroll
        for (int j = 0; j < 8; j++) {
            mx0 = fmaxf(mx0, fmaxf(s[j][0], s[j][1]));
            mx1 = fmaxf(mx1, fmaxf(s[j][2], s[j][3]));
        }
        mx0 = fmaxf(mx0, __shfl_xor_sync(0xffffffffu, mx0, 1));
        mx0 = fmaxf(mx0, __shfl_xor_sync(0xffffffffu, mx0, 2));
        mx1 = fmaxf(mx1, __shfl_xor_sync(0xffffffffu, mx1, 1));
        mx1 = fmaxf(mx1, __shfl_xor_sync(0xffffffffu, mx1, 2));
        const float mn0 = fmaxf(m0, mx0), mn1 = fmaxf(m1, mx1);
        const float cr0 = __expf(m0 - mn0), cr1 = __expf(m1 - mn1);
        float ps0 = 0.0f, ps1 = 0.0f;
#pragma unroll
        for (int j = 0; j < 8; j++) {
            s[j][0] = __expf(s[j][0] - mn0);
            s[j][1] = __expf(s[j][1] - mn0);
            s[j][2] = __expf(s[j][2] - mn1);
            s[j][3] = __expf(s[j][3] - mn1);
            ps0 += s[j][0] + s[j][1];
            ps1 += s[j][2] + s[j][3];
        }
        ps0 += __shfl_xor_sync(0xffffffffu, ps0, 1);
        ps0 += __shfl_xor_sync(0xffffffffu, ps0, 2);
        ps1 += __shfl_xor_sync(0xffffffffu, ps1, 1);
        ps1 += __shfl_xor_sync(0xffffffffu, ps1, 2);
        l0 = l0 * cr0 + ps0; m0 = mn0;
        l1 = l1 * cr1 + ps1; m1 = mn1;
#pragma unroll
        for (int j = 0; j < 8; j++) {
            o[j][0] *= cr0; o[j][1] *= cr0;
            o[j][2] *= cr1; o[j][3] *= cr1;
        }

#pragma unroll
        for (int kc = 0; kc < 4; kc++) {
            unsigned ph[4], pl[4];
            f2bf_split(s[2 * kc][0],     s[2 * kc][1],     ph[0], pl[0]);
            f2bf_split(s[2 * kc][2],     s[2 * kc][3],     ph[1], pl[1]);
            f2bf_split(s[2 * kc + 1][0], s[2 * kc + 1][1], ph[2], pl[2]);
            f2bf_split(s[2 * kc + 1][2], s[2 * kc + 1][3], ph[3], pl[3]);
            unsigned vth[4][4], vtl[4][4];
#pragma unroll
            for (int jj = 0; jj < 4; jj++) {
                const unsigned ad = swz((kc * 16 + (lane & 15)) * 128 + jj * 32 + (lane >> 4) * 16);
                ldsm4t(vth[jj], Vsh + ad);
                ldsm4t(vtl[jj], Vsl + ad);
            }
#pragma unroll
            for (int jj = 0; jj < 4; jj++) {
                unsigned bfr[2];
                bfr[0] = vth[jj][0]; bfr[1] = vth[jj][1];
                mma16816(o[2 * jj], ph, bfr);
                bfr[0] = vth[jj][2]; bfr[1] = vth[jj][3];
                mma16816(o[2 * jj + 1], ph, bfr);
            }
#pragma unroll
            for (int jj = 0; jj < 4; jj++) {
                unsigned bfr[2];
                bfr[0] = vth[jj][0]; bfr[1] = vth[jj][1];
                mma16816(o[2 * jj], pl, bfr);
                bfr[0] = vth[jj][2]; bfr[1] = vth[jj][3];
                mma16816(o[2 * jj + 1], pl, bfr);
            }
#pragma unroll
            for (int jj = 0; jj < 4; jj++) {
                unsigned bfr[2];
                bfr[0] = vtl[jj][0]; bfr[1] = vtl[jj][1];
                mma16816(o[2 * jj], ph, bfr);
                bfr[0] = vtl[jj][2]; bfr[1] = vtl[jj][3];
                mma16816(o[2 * jj + 1], ph, bfr);
            }
        }
    }

    // epilogue: normalize, write single f16 plane (A-side of output GEMM)
    const float inv0 = 1.0f / l0, inv1 = 1.0f / l1;
#pragma unroll
    for (int j = 0; j < 8; j++) {
        const size_t p0 = (size_t)(b * SEQ + qrow0) * 2048 + h * 64 + j * 8 + t2;
        __half2 v0 = __floats2half2_rn(o[j][0] * inv0, o[j][1] * inv0);
        __half2 v1 = __floats2half2_rn(o[j][2] * inv1, o[j][3] * inv1);
        *(__half2*)(O16 + p0)            = v0;
        *(__half2*)(O16 + p0 + 8 * 2048) = v1;
    }
}

// ---------------- host launcher -------------------------------------------
extern "C" void kernel_launch(void* const* d_in, const int* in_sizes, int n_in,
                              void* d_out, int out_size)
{
    const float* x    = (const float*)d_in[0];
    const int*   mask = (const int*)  d_in[1];
    const float* Wq   = (const float*)d_in[2];
    const float* Wk   = (const float*)d_in[3];
    const float* Wv   = (const float*)d_in[4];
    const float* Wo   = (const float*)d_in[5];
    float* out = (float*)d_out;

    void *pQ, *pK, *pV;
    void *px16, *pWq16h, *pWq16l, *pWk16h, *pWk16l, *pWv16h, *pWv16l, *pWo16h, *pWo16l, *pO16;
    void *pQh, *pQl, *pKh, *pKl, *pVh, *pVl;
    cudaGetSymbolAddress(&pQ, g_Q);  cudaGetSymbolAddress(&pK, g_K);
    cudaGetSymbolAddress(&pV, g_V);
    cudaGetSymbolAddress(&px16, g_x16);
    cudaGetSymbolAddress(&pWq16h, g_Wq16h); cudaGetSymbolAddress(&pWq16l, g_Wq16l);
    cudaGetSymbolAddress(&pWk16h, g_Wk16h); cudaGetSymbolAddress(&pWk16l, g_Wk16l);
    cudaGetSymbolAddress(&pWv16h, g_Wv16h); cudaGetSymbolAddress(&pWv16l, g_Wv16l);
    cudaGetSymbolAddress(&pWo16h, g_Wo16h); cudaGetSymbolAddress(&pWo16l, g_Wo16l);
    cudaGetSymbolAddress(&pO16, g_O16);
    cudaGetSymbolAddress(&pQh, g_Qh);   cudaGetSymbolAddress(&pQl, g_Ql);
    cudaGetSymbolAddress(&pKh, g_Kh);   cudaGetSymbolAddress(&pKl, g_Kl);
    cudaGetSymbolAddress(&pVh, g_Vh);   cudaGetSymbolAddress(&pVl, g_Vl);

    init_freqs_kernel<<<1, 32>>>();

    // f16 planes: x single, weights hi+lo
    split16_kernel<<<(MROWS * DMODEL / 4) / 256, 256>>>(x, (__half*)px16, MROWS * DMODEL / 4);
    wsplit16_kernel<<<(DMODEL * 2048 / 4) / 256, 256>>>(Wq, (__half*)pWq16h, (__half*)pWq16l, DMODEL * 2048 / 4);
    wsplit16_kernel<<<(DMODEL * 512  / 4) / 256, 256>>>(Wk, (__half*)pWk16h, (__half*)pWk16l, DMODEL * 512 / 4);
    wsplit16_kernel<<<(DMODEL * 512  / 4) / 256, 256>>>(Wv, (__half*)pWv16h, (__half*)pWv16l, DMODEL * 512 / 4);
    wsplit16_kernel<<<(2048 * DMODEL / 4) / 256, 256>>>(Wo, (__half*)pWo16h, (__half*)pWo16l, 2048 * DMODEL / 4);

    cudaFuncSetAttribute(gemm_f16x2, cudaFuncAttributeMaxDynamicSharedMemorySize, GEMM_SMEM);

    // QKV projections (f16 2-product)
    gemm_f16x2<<<dim3(2048 / 128, MROWS / 128), 256, GEMM_SMEM>>>(
        (const __half*)px16, (const __half*)pWq16h, (const __half*)pWq16l,
        (float*)pQ, MROWS, 2048, DMODEL);
    gemm_f16x2<<<dim3(512 / 128, MROWS / 128), 256, GEMM_SMEM>>>(
        (const __half*)px16, (const __half*)pWk16h, (const __half*)pWk16l,
        (float*)pK, MROWS, 512, DMODEL);
    gemm_f16x2<<<dim3(512 / 128, MROWS / 128), 256, GEMM_SMEM>>>(
        (const __half*)px16, (const __half*)pWv16h, (const __half*)pWv16l,
        (float*)pV, MROWS, 512, DMODEL);

    // fused RoPE + split for Q and K; plain split for V (bf16 planes for flash)
    rope_split_kernel<<<(MROWS * NHEADS  * 32) / 256, 256>>>(
        (const float*)pQ, (__nv_bfloat16*)pQh, (__nv_bfloat16*)pQl, NHEADS * HDIM, NHEADS);
    rope_split_kernel<<<(MROWS * KVHEADS * 32) / 256, 256>>>(
        (const float*)pK, (__nv_bfloat16*)pKh, (__nv_bfloat16*)pKl, KVHEADS * HDIM, KVHEADS);
    split_kernel<<<(MROWS * 512 / 4) / 256, 256>>>(
        (const float*)pV, (__nv_bfloat16*)pVh, (__nv_bfloat16*)pVl, MROWS * 512 / 4);

    // Flash attention (tensor cores, split-bf16), emits f16 O plane
    cudaFuncSetAttribute(flash_mma_kernel, cudaFuncAttributeMaxDynamicSharedMemorySize, FL_SMEM);
    flash_mma_kernel<<<dim3(SEQ / 64, NHEADS, BATCH), 128, FL_SMEM>>>(
        (const __nv_bfloat16*)pQh, (const __nv_bfloat16*)pQl,
        (const __nv_bfloat16*)pKh, (const __nv_bfloat16*)pKl,
        (const __nv_bfloat16*)pVh, (const __nv_bfloat16*)pVl,
        mask, (__half*)pO16);

    // Output projection (f16 2-product)
    gemm_f16x2<<<dim3(2048 / 128, MROWS / 128), 256, GEMM_SMEM>>>(
        (const __half*)pO16, (const __half*)pWo16h, (const __half*)pWo16l,
        out, MROWS, 2048, DMODEL);
}

// round 14
// speedup vs baseline: 1.7660x; 1.1926x over previous
#include <cuda_runtime.h>
#include <cuda_bf16.h>
#include <cuda_fp16.h>
#include <math.h>
#include <stdint.h>

#define BATCH   2
#define SEQ     2048
#define DMODEL  2048
#define NHEADS  32
#define HDIM    64
#define KVHEADS 8
#define MROWS   (BATCH*SEQ)          // 4096

// ---------------- scratch (device globals; no allocation allowed) ----------
__device__ float g_Q[MROWS * NHEADS * HDIM];
__device__ float g_K[MROWS * KVHEADS * HDIM];
__device__ float g_V[MROWS * KVHEADS * HDIM];
__device__ float g_freqs[32];

// f16 planes for GEMMs (A-side single plane; weights hi+lo)
__device__ __half g_x16 [MROWS * DMODEL];
__device__ __half g_Wq16h[DMODEL * 2048];
__device__ __half g_Wq16l[DMODEL * 2048];
__device__ __half g_Wk16h[DMODEL * 512];
__device__ __half g_Wk16l[DMODEL * 512];
__device__ __half g_Wv16h[DMODEL * 512];
__device__ __half g_Wv16l[DMODEL * 512];
__device__ __half g_Wo16h[2048 * DMODEL];
__device__ __half g_Wo16l[2048 * DMODEL];
__device__ __half g_O16 [MROWS * 2048];

// f16 single planes for flash
__device__ __half g_Q16 [MROWS * 2048];
__device__ __half g_K16 [MROWS * 512];
__device__ __half g_V16 [MROWS * 512];

// ---------------- RoPE frequency table -------------------------------------
__global__ void init_freqs_kernel() {
    int i = threadIdx.x;
    g_freqs[i] = (float)exp2(-(double)i * (13.287712379549449 / 32.0));
}

// ---------------- fp32 -> f16 single plane ----------------------------------
__global__ void __launch_bounds__(256) split16_kernel(
    const float* __restrict__ src, __half* __restrict__ dst, int n4)
{
    const int i = blockIdx.x * blockDim.x + threadIdx.x;
    if (i >= n4) return;
    const float4 f = ((const float4*)src)[i];
    __half2 a = __floats2half2_rn(f.x, f.y);
    __half2 b = __floats2half2_rn(f.z, f.w);
    uint2 v; v.x = *(unsigned*)&a; v.y = *(unsigned*)&b;
    *(uint2*)(dst + 4 * (size_t)i) = v;
}

// ---------------- fp32 weights -> f16 (hi, lo) planes -----------------------
__global__ void __launch_bounds__(256) wsplit16_kernel(
    const float* __restrict__ src, __half* __restrict__ hi,
    __half* __restrict__ lo, int n4)
{
    const int i = blockIdx.x * blockDim.x + threadIdx.x;
    if (i >= n4) return;
    const float4 f = ((const float4*)src)[i];
    const float fv[4] = {f.x, f.y, f.z, f.w};
    __half h[4], l[4];
#pragma unroll
    for (int k = 0; k < 4; k++) {
        h[k] = __float2half_rn(fv[k]);
        l[k] = __float2half_rn(fv[k] - __half2float(h[k]));
    }
    *(uint2*)(hi + 4 * (size_t)i) = *(uint2*)h;
    *(uint2*)(lo + 4 * (size_t)i) = *(uint2*)l;
}

// ---------------- PTX helpers ----------------------------------------------
__device__ __forceinline__ void cpasync16(void* s, const void* g) {
    unsigned sa = (unsigned)__cvta_generic_to_shared(s);
    asm volatile("cp.async.cg.shared.global [%0], [%1], 16;\n" :: "r"(sa), "l"(g));
}
__device__ __forceinline__ void cp_commit() {
    asm volatile("cp.async.commit_group;\n" ::: "memory");
}
__device__ __forceinline__ void cp_wait0() {
    asm volatile("cp.async.wait_group 0;\n" ::: "memory");
}
__device__ __forceinline__ void cp_wait1() {
    asm volatile("cp.async.wait_group 1;\n" ::: "memory");
}
__device__ __forceinline__ void ldsm4(unsigned* r, const void* p) {
    unsigned a = (unsigned)__cvta_generic_to_shared(p);
    asm volatile("ldmatrix.sync.aligned.m8n8.x4.shared.b16 {%0,%1,%2,%3}, [%4];"
                 : "=r"(r[0]), "=r"(r[1]), "=r"(r[2]), "=r"(r[3]) : "r"(a));
}
__device__ __forceinline__ void ldsm4t(unsigned* r, const void* p) {
    unsigned a = (unsigned)__cvta_generic_to_shared(p);
    asm volatile("ldmatrix.sync.aligned.m8n8.x4.trans.shared.b16 {%0,%1,%2,%3}, [%4];"
                 : "=r"(r[0]), "=r"(r[1]), "=r"(r[2]), "=r"(r[3]) : "r"(a));
}
__device__ __forceinline__ void mma16816h(float* d, const unsigned* a, const unsigned* b) {
    asm volatile("mma.sync.aligned.m16n8k16.row.col.f32.f16.f16.f32 "
                 "{%0,%1,%2,%3},{%4,%5,%6,%7},{%8,%9},{%0,%1,%2,%3};"
                 : "+f"(d[0]), "+f"(d[1]), "+f"(d[2]), "+f"(d[3])
                 : "r"(a[0]), "r"(a[1]), "r"(a[2]), "r"(a[3]), "r"(b[0]), "r"(b[1]));
}
__device__ __forceinline__ unsigned swz(unsigned o) { return o ^ ((o >> 3) & 0x70); }

__device__ __forceinline__ unsigned f2h2(float x, float y) {
    __half2 h = __floats2half2_rn(x, y);
    return *(unsigned*)&h;
}

// ---------------- f16 2-product GEMM ----------------------------------------
// C = Ah*Bh + Ah*Bl, f32 accum. Ah = f16(A) [M,K]; Bh = f16(B), Bl = f16(B-Bh).
#define SA_STRIDE 56
#define SB_STRIDE 136
#define SA_PLANE  (128 * SA_STRIDE)
#define SB_PLANE  (32 * SB_STRIDE)
#define STAGE_ELEMS (SA_PLANE + 2 * SB_PLANE)
#define GEMM_SMEM (3 * STAGE_ELEMS * 2)

__global__ void __launch_bounds__(256, 1) gemm_f16x2(
    const __half* __restrict__ Ah,
    const __half* __restrict__ Bh, const __half* __restrict__ Bl,
    float* __restrict__ C, int M, int N, int K)
{
    extern __shared__ __half sm[];
    const int tid  = threadIdx.x;
    const int warp = tid >> 5, lane = tid & 31;
    const int bm = blockIdx.y * 128, bn = blockIdx.x * 128;
    const int wm = (warp >> 2) * 64, wn = (warp & 3) * 32;

    float acc[4][4][4];
#pragma unroll
    for (int i = 0; i < 4; i++)
#pragma unroll
        for (int j = 0; j < 4; j++)
#pragma unroll
            for (int d = 0; d < 4; d++) acc[i][j][d] = 0.0f;

    const int kIters = K >> 5;

#define LOAD_STAGE(s, k0) do {                                                  \
        __half* Sah = sm + (s) * STAGE_ELEMS;                                   \
        __half* Sbh = Sah + SA_PLANE;                                           \
        __half* Sbl = Sbh + SB_PLANE;                                           \
        _Pragma("unroll")                                                       \
        for (int cc = 0; cc < 2; cc++) {                                        \
            const int c  = tid + cc * 256;                                      \
            const int ar = c >> 2, ac = c & 3;                                  \
            cpasync16(Sah + ar * SA_STRIDE + ac * 8,                            \
                      Ah + (size_t)(bm + ar) * K + (k0) + ac * 8);              \
            const int br = c >> 4, bc = c & 15;                                 \
            const size_t gb = (size_t)((k0) + br) * N + bn + bc * 8;            \
            cpasync16(Sbh + br * SB_STRIDE + bc * 8, Bh + gb);                  \
            cpasync16(Sbl + br * SB_STRIDE + bc * 8, Bl + gb);                  \
        }                                                                       \
        cp_commit();                                                            \
    } while (0)

    LOAD_STAGE(0, 0);
    LOAD_STAGE(1, 32);

    for (int it = 0; it < kIters; it++) {
        const int s = it % 3;
        if (it + 1 < kIters) cp_wait1(); else cp_wait0();
        __syncthreads();
        if (it + 2 < kIters) LOAD_STAGE((it + 2) % 3, (it + 2) * 32);

        const __half* Sah = sm + s * STAGE_ELEMS;
        const __half* Sbh = Sah + SA_PLANE;
        const __half* Sbl = Sbh + SB_PLANE;

#pragma unroll
        for (int kk = 0; kk < 2; kk++) {
            unsigned ah[4][4];
#pragma unroll
            for (int i = 0; i < 4; i++)
                ldsm4(ah[i], Sah + (wm + i * 16 + (lane & 15)) * SA_STRIDE
                              + kk * 16 + (lane >> 4) * 8);
            unsigned bh[4][2], bl[4][2];
#pragma unroll
            for (int jj = 0; jj < 2; jj++) {
                const int off = (kk * 16 + (lane & 15)) * SB_STRIDE
                              + wn + jj * 16 + (lane >> 4) * 8;
                unsigned t[4];
                ldsm4t(t, Sbh + off);
                bh[2 * jj][0] = t[0]; bh[2 * jj][1] = t[1];
                bh[2 * jj + 1][0] = t[2]; bh[2 * jj + 1][1] = t[3];
                ldsm4t(t, Sbl + off);
                bl[2 * jj][0] = t[0]; bl[2 * jj][1] = t[1];
                bl[2 * jj + 1][0] = t[2]; bl[2 * jj + 1][1] = t[3];
            }
#pragma unroll
            for (int i = 0; i < 4; i++)
#pragma unroll
                for (int j = 0; j < 4; j++)
                    mma16816h(acc[i][j], ah[i], bh[j]);
#pragma unroll
            for (int i = 0; i < 4; i++)
#pragma unroll
                for (int j = 0; j < 4; j++)
                    mma16816h(acc[i][j], ah[i], bl[j]);
        }
    }

    // epilogue
#pragma unroll
    for (int i = 0; i < 4; i++)
#pragma unroll
        for (int j = 0; j < 4; j++) {
            const int r = bm + wm + i * 16 + (lane >> 2);
            const int c = bn + wn + j * 8 + (lane & 3) * 2;
            *(float2*)(C + (size_t)r * N + c)       = make_float2(acc[i][j][0], acc[i][j][1]);
            *(float2*)(C + (size_t)(r + 8) * N + c) = make_float2(acc[i][j][2], acc[i][j][3]);
        }
}

// ---------------- fused RoPE + f16 convert ----------------------------------
__global__ void rope_f16_kernel(
    const float* __restrict__ buf, __half* __restrict__ dst, int rowlen, int heads)
{
    const int idx = blockIdx.x * blockDim.x + threadIdx.x;
    const int total = MROWS * heads * 32;
    if (idx >= total) return;
    const int j  = idx & 31;
    const int t1 = idx >> 5;
    const int h  = t1 % heads;
    const int r  = t1 / heads;
    const float tn = (float)(r & (SEQ - 1));

    const size_t base = (size_t)r * rowlen + h * HDIM;
    const float x1 = buf[base + j];
    const float x2 = buf[base + j + 32];

    const float a1 = tn * g_freqs[j >> 1];
    const float a2 = tn * g_freqs[16 + (j >> 1)];
    float s1, c1, s2, c2;
    sincosf(a1, &s1, &c1);
    sincosf(a2, &s2, &c2);
    dst[base + j]      = __float2half_rn(x1 * c1 - x2 * s1);
    dst[base + j + 32] = __float2half_rn(x1 * s2 + x2 * c2);
}

// ---------------- Flash attention, full f16 single-plane --------------------
// smem: Qs 8KB + Ks 8KB + Vs 8KB + bias 256B = 24832 B
#define FL_SMEM (3 * 8192 + 256)

__global__ void __launch_bounds__(128, 3) flash_f16_kernel(
    const __half* __restrict__ Q16, const __half* __restrict__ K16,
    const __half* __restrict__ V16, const int* __restrict__ mask,
    __half* __restrict__ O16)
{
    extern __shared__ char smc[];
    char* Qs = smc;
    char* Ks = smc + 8192;
    char* Vs = smc + 16384;
    float* bias = (float*)(smc + 24576);

    const int qt = (gridDim.x - 1) - blockIdx.x;
    const int h = blockIdx.y, b = blockIdx.z;
    const int kvh = h >> 2;
    const int tid = threadIdx.x, warp = tid >> 5, lane = tid & 31;
    const int g = lane >> 2, t2 = (lane & 3) * 2;
    const float scale = 0.125f;
    const float slope = exp2f(-0.25f * (float)(h + 1));

    // ---- load Q tile (64x64 f16) ----
    {
        const size_t base = (size_t)(b * SEQ + qt * 64) * 2048 + h * 64;
#pragma unroll
        for (int cc = 0; cc < 4; cc++) {
            const int c = tid + cc * 128;
            const int row = c >> 3, k8 = c & 7;
            cpasync16(Qs + swz(row * 128 + k8 * 16), Q16 + base + (size_t)row * 2048 + k8 * 8);
        }
        cp_commit(); cp_wait0();
        __syncthreads();
    }
    unsigned qf[4][4];
#pragma unroll
    for (int kc = 0; kc < 4; kc++)
        ldsm4(qf[kc], Qs + swz((warp * 16 + (lane & 15)) * 128 + kc * 32 + (lane >> 4) * 16));

    float o[8][4];
#pragma unroll
    for (int j = 0; j < 8; j++)
#pragma unroll
        for (int d = 0; d < 4; d++) o[j][d] = 0.0f;
    float m0 = -1e30f, m1 = -1e30f, l0 = 0.0f, l1 = 0.0f;
    const int qrow0 = qt * 64 + warp * 16 + g;

    for (int kt = 0; kt <= qt; kt++) {
        __syncthreads();
        {
            const size_t kbase = (size_t)(b * SEQ + kt * 64) * 512 + kvh * 64;
#pragma unroll
            for (int cc = 0; cc < 4; cc++) {
                const int c = tid + cc * 128;
                const int row = c >> 3, k8 = c & 7;
                const size_t gp = kbase + (size_t)row * 512 + k8 * 8;
                const unsigned so = swz(row * 128 + k8 * 16);
                cpasync16(Ks + so, K16 + gp);
                cpasync16(Vs + so, V16 + gp);
            }
        }
        if (tid < 64) bias[tid] = mask[b * SEQ + kt * 64 + tid] ? 0.0f : -1e30f;
        cp_commit(); cp_wait0();
        __syncthreads();

        // ---- S = Q K^T (single f16 product) ----
        float s[8][4];
#pragma unroll
        for (int j = 0; j < 8; j++)
#pragma unroll
            for (int d = 0; d < 4; d++) s[j][d] = 0.0f;

#pragma unroll
        for (int kc = 0; kc < 4; kc++)
#pragma unroll
            for (int jj = 0; jj < 4; jj++) {
                unsigned kt4[4];
                ldsm4(kt4, Ks + swz((jj * 16 + (lane & 15)) * 128 + kc * 32 + (lane >> 4) * 16));
                unsigned bfr[2];
                bfr[0] = kt4[0]; bfr[1] = kt4[2];
                mma16816h(s[2 * jj], qf[kc], bfr);
                bfr[0] = kt4[1]; bfr[1] = kt4[3];
                mma16816h(s[2 * jj + 1], qf[kc], bfr);
            }

        // ---- scale + ALiBi + causal + pad ----
#pragma unroll
        for (int j = 0; j < 8; j++) {
            const int kg = kt * 64 + j * 8 + t2;
            const float b0 = bias[j * 8 + t2];
            const float b1 = bias[j * 8 + t2 + 1];
            const float al0 = fmaf(slope, (float)kg, b0);
            const float al1 = fmaf(slope, (float)(kg + 1), b1);
            float v0 = fmaf(s[j][0], scale, al0);
            float v1 = fmaf(s[j][1], scale, al1);
            float v2 = fmaf(s[j][2], scale, al0);
            float v3 = fmaf(s[j][3], scale, al1);
            if (kg     > qrow0)     v0 = -1e30f;
            if (kg + 1 > qrow0)     v1 = -1e30f;
            if (kg     > qrow0 + 8) v2 = -1e30f;
            if (kg + 1 > qrow0 + 8) v3 = -1e30f;
            s[j][0] = v0; s[j][1] = v1; s[j][2] = v2; s[j][3] = v3;
        }

        // ---- online softmax ----
        float mx0 = -1e30f, mx1 = -1e30f;
#pragma unroll
        for (int j = 0; j < 8; j++) {
            mx0 = fmaxf(mx0, fmaxf(s[j][0], s[j][1]));
            mx1 = fmaxf(mx1, fmaxf(s[j][2], s[j][3]));
        }
        mx0 = fmaxf(mx0, __shfl_xor_sync(0xffffffffu, mx0, 1));
        mx0 = fmaxf(mx0, __shfl_xor_sync(0xffffffffu, mx0, 2));
        mx1 = fmaxf(mx1, __shfl_xor_sync(0xffffffffu, mx1, 1));
        mx1 = fmaxf(mx1, __shfl_xor_sync(0xffffffffu, mx1, 2));
        const float mn0 = fmaxf(m0, mx0), mn1 = fmaxf(m1, mx1);
        const float cr0 = __expf(m0 - mn0), cr1 = __expf(m1 - mn1);
        float ps0 = 0.0f, ps1 = 0.0f;
#pragma unroll
        for (int j = 0; j < 8; j++) {
            s[j][0] = __expf(s[j][0] - mn0);
            s[j][1] = __expf(s[j][1] - mn0);
            s[j][2] = __expf(s[j][2] - mn1);
            s[j][3] = __expf(s[j][3] - mn1);
            ps0 += s[j][0] + s[j][1];
            ps1 += s[j][2] + s[j][3];
        }
        ps0 += __shfl_xor_sync(0xffffffffu, ps0, 1);
        ps0 += __shfl_xor_sync(0xffffffffu, ps0, 2);
        ps1 += __shfl_xor_sync(0xffffffffu, ps1, 1);
        ps1 += __shfl_xor_sync(0xffffffffu, ps1, 2);
        l0 = l0 * cr0 + ps0; m0 = mn0;
        l1 = l1 * cr1 + ps1; m1 = mn1;
#pragma unroll
        for (int j = 0; j < 8; j++) {
            o[j][0] *= cr0; o[j][1] *= cr0;
            o[j][2] *= cr1; o[j][3] *= cr1;
        }

        // ---- O += P V (single f16 product) ----
#pragma unroll
        for (int kc = 0; kc < 4; kc++) {
            unsigned pf[4];
            pf[0] = f2h2(s[2 * kc][0],     s[2 * kc][1]);
            pf[1] = f2h2(s[2 * kc][2],     s[2 * kc][3]);
            pf[2] = f2h2(s[2 * kc + 1][0], s[2 * kc + 1][1]);
            pf[3] = f2h2(s[2 * kc + 1][2], s[2 * kc + 1][3]);
#pragma unroll
            for (int jj = 0; jj < 4; jj++) {
                unsigned vt4[4];
                ldsm4t(vt4, Vs + swz((kc * 16 + (lane & 15)) * 128 + jj * 32 + (lane >> 4) * 16));
                unsigned bfr[2];
                bfr[0] = vt4[0]; bfr[1] = vt4[1];
                mma16816h(o[2 * jj], pf, bfr);
                bfr[0] = vt4[2]; bfr[1] = vt4[3];
                mma16816h(o[2 * jj + 1], pf, bfr);
            }
        }
    }

    // epilogue: normalize, write single f16 plane (A-side of output GEMM)
    const float inv0 = 1.0f / l0, inv1 = 1.0f / l1;
#pragma unroll
    for (int j = 0; j < 8; j++) {
        const size_t p0 = (size_t)(b * SEQ + qrow0) * 2048 + h * 64 + j * 8 + t2;
        *(unsigned*)(O16 + p0)            = f2h2(o[j][0] * inv0, o[j][1] * inv0);
        *(unsigned*)(O16 + p0 + 8 * 2048) = f2h2(o[j][2] * inv1, o[j][3] * inv1);
    }
}

// ---------------- host launcher -------------------------------------------
extern "C" void kernel_launch(void* const* d_in, const int* in_sizes, int n_in,
                              void* d_out, int out_size)
{
    const float* x    = (const float*)d_in[0];
    const int*   mask = (const int*)  d_in[1];
    const float* Wq   = (const float*)d_in[2];
    const float* Wk   = (const float*)d_in[3];
    const float* Wv   = (const float*)d_in[4];
    const float* Wo   = (const float*)d_in[5];
    float* out = (float*)d_out;

    void *pQ, *pK, *pV;
    void *px16, *pWq16h, *pWq16l, *pWk16h, *pWk16l, *pWv16h, *pWv16l, *pWo16h, *pWo16l, *pO16;
    void *pQ16, *pK16, *pV16;
    cudaGetSymbolAddress(&pQ, g_Q);  cudaGetSymbolAddress(&pK, g_K);
    cudaGetSymbolAddress(&pV, g_V);
    cudaGetSymbolAddress(&px16, g_x16);
    cudaGetSymbolAddress(&pWq16h, g_Wq16h); cudaGetSymbolAddress(&pWq16l, g_Wq16l);
    cudaGetSymbolAddress(&pWk16h, g_Wk16h); cudaGetSymbolAddress(&pWk16l, g_Wk16l);
    cudaGetSymbolAddress(&pWv16h, g_Wv16h); cudaGetSymbolAddress(&pWv16l, g_Wv16l);
    cudaGetSymbolAddress(&pWo16h, g_Wo16h); cudaGetSymbolAddress(&pWo16l, g_Wo16l);
    cudaGetSymbolAddress(&pO16, g_O16);
    cudaGetSymbolAddress(&pQ16, g_Q16);
    cudaGetSymbolAddress(&pK16, g_K16);
    cudaGetSymbolAddress(&pV16, g_V16);

    init_freqs_kernel<<<1, 32>>>();

    // f16 planes: x single, weights hi+lo
    split16_kernel<<<(MROWS * DMODEL / 4) / 256, 256>>>(x, (__half*)px16, MROWS * DMODEL / 4);
    wsplit16_kernel<<<(DMODEL * 2048 / 4) / 256, 256>>>(Wq, (__half*)pWq16h, (__half*)pWq16l, DMODEL * 2048 / 4);
    wsplit16_kernel<<<(DMODEL * 512  / 4) / 256, 256>>>(Wk, (__half*)pWk16h, (__half*)pWk16l, DMODEL * 512 / 4);
    wsplit16_kernel<<<(DMODEL * 512  / 4) / 256, 256>>>(Wv, (__half*)pWv16h, (__half*)pWv16l, DMODEL * 512 / 4);
    wsplit16_kernel<<<(2048 * DMODEL / 4) / 256, 256>>>(Wo, (__half*)pWo16h, (__half*)pWo16l, 2048 * DMODEL / 4);

    cudaFuncSetAttribute(gemm_f16x2, cudaFuncAttributeMaxDynamicSharedMemorySize, GEMM_SMEM);

    // QKV projections (f16 2-product)
    gemm_f16x2<<<dim3(2048 / 128, MROWS / 128), 256, GEMM_SMEM>>>(
        (const __half*)px16, (const __half*)pWq16h, (const __half*)pWq16l,
        (float*)pQ, MROWS, 2048, DMODEL);
    gemm_f16x2<<<dim3(512 / 128, MROWS / 128), 256, GEMM_SMEM>>>(
        (const __half*)px16, (const __half*)pWk16h, (const __half*)pWk16l,
        (float*)pK, MROWS, 512, DMODEL);
    gemm_f16x2<<<dim3(512 / 128, MROWS / 128), 256, GEMM_SMEM>>>(
        (const __half*)px16, (const __half*)pWv16h, (const __half*)pWv16l,
        (float*)pV, MROWS, 512, DMODEL);

    // fused RoPE + f16 for Q and K; plain f16 for V
    rope_f16_kernel<<<(MROWS * NHEADS  * 32) / 256, 256>>>(
        (const float*)pQ, (__half*)pQ16, NHEADS * HDIM, NHEADS);
    rope_f16_kernel<<<(MROWS * KVHEADS * 32) / 256, 256>>>(
        (const float*)pK, (__half*)pK16, KVHEADS * HDIM, KVHEADS);
    split16_kernel<<<(MROWS * 512 / 4) / 256, 256>>>(
        (const float*)pV, (__half*)pV16, MROWS * 512 / 4);

    // Flash attention (full f16 single-plane)
    cudaFuncSetAttribute(flash_f16_kernel, cudaFuncAttributeMaxDynamicSharedMemorySize, FL_SMEM);
    flash_f16_kernel<<<dim3(SEQ / 64, NHEADS, BATCH), 128, FL_SMEM>>>(
        (const __half*)pQ16, (const __half*)pK16, (const __half*)pV16,
        mask, (__half*)pO16);

    // Output projection (f16 2-product)
    gemm_f16x2<<<dim3(2048 / 128, MROWS / 128), 256, GEMM_SMEM>>>(
        (const __half*)pO16, (const __half*)pWo16h, (const __half*)pWo16l,
        out, MROWS, 2048, DMODEL);
}

// round 16
// speedup vs baseline: 2.5737x; 1.4573x over previous
#include <cuda_runtime.h>
#include <cuda_bf16.h>
#include <cuda_fp16.h>
#include <math.h>
#include <stdint.h>

#define BATCH   2
#define SEQ     2048
#define DMODEL  2048
#define NHEADS  32
#define HDIM    64
#define KVHEADS 8
#define MROWS   (BATCH*SEQ)          // 4096

// ---------------- scratch (device globals; no allocation allowed) ----------
__device__ float g_Q[MROWS * NHEADS * HDIM];
__device__ float g_K[MROWS * KVHEADS * HDIM];
__device__ float g_V[MROWS * KVHEADS * HDIM];
__device__ float g_freqs[32];

// f16 planes
__device__ __half g_x16 [MROWS * DMODEL];
__device__ __half g_Wq16[DMODEL * 2048];
__device__ __half g_Wk16[DMODEL * 512];
__device__ __half g_Wv16[DMODEL * 512];
__device__ __half g_Wo16[2048 * DMODEL];
__device__ __half g_O16 [MROWS * 2048];
__device__ __half g_Q16 [MROWS * 2048];
__device__ __half g_K16 [MROWS * 512];
__device__ __half g_V16 [MROWS * 512];

// ---------------- RoPE frequency table -------------------------------------
__global__ void init_freqs_kernel() {
    int i = threadIdx.x;
    g_freqs[i] = (float)exp2(-(double)i * (13.287712379549449 / 32.0));
}

// ---------------- fp32 -> f16 single plane ----------------------------------
__global__ void __launch_bounds__(256) split16_kernel(
    const float* __restrict__ src, __half* __restrict__ dst, int n4)
{
    const int i = blockIdx.x * blockDim.x + threadIdx.x;
    if (i >= n4) return;
    const float4 f = ((const float4*)src)[i];
    __half2 a = __floats2half2_rn(f.x, f.y);
    __half2 b = __floats2half2_rn(f.z, f.w);
    uint2 v; v.x = *(unsigned*)&a; v.y = *(unsigned*)&b;
    *(uint2*)(dst + 4 * (size_t)i) = v;
}

// ---------------- PTX helpers ----------------------------------------------
__device__ __forceinline__ void cpasync16(void* s, const void* g) {
    unsigned sa = (unsigned)__cvta_generic_to_shared(s);
    asm volatile("cp.async.cg.shared.global [%0], [%1], 16;\n" :: "r"(sa), "l"(g));
}
__device__ __forceinline__ void cp_commit() {
    asm volatile("cp.async.commit_group;\n" ::: "memory");
}
__device__ __forceinline__ void cp_wait0() {
    asm volatile("cp.async.wait_group 0;\n" ::: "memory");
}
__device__ __forceinline__ void cp_wait1() {
    asm volatile("cp.async.wait_group 1;\n" ::: "memory");
}
__device__ __forceinline__ void ldsm4(unsigned* r, const void* p) {
    unsigned a = (unsigned)__cvta_generic_to_shared(p);
    asm volatile("ldmatrix.sync.aligned.m8n8.x4.shared.b16 {%0,%1,%2,%3}, [%4];"
                 : "=r"(r[0]), "=r"(r[1]), "=r"(r[2]), "=r"(r[3]) : "r"(a));
}
__device__ __forceinline__ void ldsm4t(unsigned* r, const void* p) {
    unsigned a = (unsigned)__cvta_generic_to_shared(p);
    asm volatile("ldmatrix.sync.aligned.m8n8.x4.trans.shared.b16 {%0,%1,%2,%3}, [%4];"
                 : "=r"(r[0]), "=r"(r[1]), "=r"(r[2]), "=r"(r[3]) : "r"(a));
}
__device__ __forceinline__ void mma16816h(float* d, const unsigned* a, const unsigned* b) {
    asm volatile("mma.sync.aligned.m16n8k16.row.col.f32.f16.f16.f32 "
                 "{%0,%1,%2,%3},{%4,%5,%6,%7},{%8,%9},{%0,%1,%2,%3};"
                 : "+f"(d[0]), "+f"(d[1]), "+f"(d[2]), "+f"(d[3])
                 : "r"(a[0]), "r"(a[1]), "r"(a[2]), "r"(a[3]), "r"(b[0]), "r"(b[1]));
}
__device__ __forceinline__ unsigned swz(unsigned o) { return o ^ ((o >> 3) & 0x70); }

__device__ __forceinline__ unsigned f2h2(float x, float y) {
    __half2 h = __floats2half2_rn(x, y);
    return *(unsigned*)&h;
}

// ---------------- f16 single-product GEMM ------------------------------------
// C = A*B, f32 accum. A f16 [M,K]; B f16 [K,N]. BM=128 BN=128 BK=32, 256 thr.
#define SA_STRIDE 56
#define SB_STRIDE 136
#define SA_PLANE  (128 * SA_STRIDE)   // 7168 elems
#define SB_PLANE  (32 * SB_STRIDE)    // 4352 elems
#define STAGE_ELEMS (SA_PLANE + SB_PLANE)   // 11520 elems = 23040 B
#define GEMM_SMEM (3 * STAGE_ELEMS * 2)     // 69120 B (3 stages)

__global__ void __launch_bounds__(256) gemm_f16(
    const __half* __restrict__ A,
    const __half* __restrict__ B,
    float* __restrict__ C, int M, int N, int K)
{
    extern __shared__ __half sm[];
    const int tid  = threadIdx.x;
    const int warp = tid >> 5, lane = tid & 31;
    const int bm = blockIdx.y * 128, bn = blockIdx.x * 128;
    const int wm = (warp >> 2) * 64, wn = (warp & 3) * 32;

    float acc[4][4][4];
#pragma unroll
    for (int i = 0; i < 4; i++)
#pragma unroll
        for (int j = 0; j < 4; j++)
#pragma unroll
            for (int d = 0; d < 4; d++) acc[i][j][d] = 0.0f;

    const int kIters = K >> 5;

#define LOAD_STAGE(s, k0) do {                                                  \
        __half* Sa = sm + (s) * STAGE_ELEMS;                                    \
        __half* Sb = Sa + SA_PLANE;                                             \
        _Pragma("unroll")                                                       \
        for (int cc = 0; cc < 2; cc++) {                                        \
            const int c  = tid + cc * 256;                                      \
            const int ar = c >> 2, ac = c & 3;                                  \
            cpasync16(Sa + ar * SA_STRIDE + ac * 8,                             \
                      A + (size_t)(bm + ar) * K + (k0) + ac * 8);               \
            const int br = c >> 4, bc = c & 15;                                 \
            cpasync16(Sb + br * SB_STRIDE + bc * 8,                             \
                      B + (size_t)((k0) + br) * N + bn + bc * 8);               \
        }                                                                       \
        cp_commit();                                                            \
    } while (0)

    LOAD_STAGE(0, 0);
    LOAD_STAGE(1, 32);

    for (int it = 0; it < kIters; it++) {
        const int s = it % 3;
        if (it + 1 < kIters) cp_wait1(); else cp_wait0();
        __syncthreads();
        if (it + 2 < kIters) LOAD_STAGE((it + 2) % 3, (it + 2) * 32);

        const __half* Sa = sm + s * STAGE_ELEMS;
        const __half* Sb = Sa + SA_PLANE;

#pragma unroll
        for (int kk = 0; kk < 2; kk++) {
            unsigned af[4][4];
#pragma unroll
            for (int i = 0; i < 4; i++)
                ldsm4(af[i], Sa + (wm + i * 16 + (lane & 15)) * SA_STRIDE
                              + kk * 16 + (lane >> 4) * 8);
            unsigned bf[4][2];
#pragma unroll
            for (int jj = 0; jj < 2; jj++) {
                unsigned t[4];
                ldsm4t(t, Sb + (kk * 16 + (lane & 15)) * SB_STRIDE
                           + wn + jj * 16 + (lane >> 4) * 8);
                bf[2 * jj][0] = t[0]; bf[2 * jj][1] = t[1];
                bf[2 * jj + 1][0] = t[2]; bf[2 * jj + 1][1] = t[3];
            }
#pragma unroll
            for (int i = 0; i < 4; i++)
#pragma unroll
                for (int j = 0; j < 4; j++)
                    mma16816h(acc[i][j], af[i], bf[j]);
        }
    }

    // epilogue
#pragma unroll
    for (int i = 0; i < 4; i++)
#pragma unroll
        for (int j = 0; j < 4; j++) {
            const int r = bm + wm + i * 16 + (lane >> 2);
            const int c = bn + wn + j * 8 + (lane & 3) * 2;
            *(float2*)(C + (size_t)r * N + c)       = make_float2(acc[i][j][0], acc[i][j][1]);
            *(float2*)(C + (size_t)(r + 8) * N + c) = make_float2(acc[i][j][2], acc[i][j][3]);
        }
}

// ---------------- fused RoPE + f16 convert ----------------------------------
__global__ void rope_f16_kernel(
    const float* __restrict__ buf, __half* __restrict__ dst, int rowlen, int heads)
{
    const int idx = blockIdx.x * blockDim.x + threadIdx.x;
    const int total = MROWS * heads * 32;
    if (idx >= total) return;
    const int j  = idx & 31;
    const int t1 = idx >> 5;
    const int h  = t1 % heads;
    const int r  = t1 / heads;
    const float tn = (float)(r & (SEQ - 1));

    const size_t base = (size_t)r * rowlen + h * HDIM;
    const float x1 = buf[base + j];
    const float x2 = buf[base + j + 32];

    const float a1 = tn * g_freqs[j >> 1];
    const float a2 = tn * g_freqs[16 + (j >> 1)];
    float s1, c1, s2, c2;
    sincosf(a1, &s1, &c1);
    sincosf(a2, &s2, &c2);
    dst[base + j]      = __float2half_rn(x1 * c1 - x2 * s1);
    dst[base + j + 32] = __float2half_rn(x1 * s2 + x2 * c2);
}

// ---------------- Flash attention, full f16 single-plane --------------------
#define FL_SMEM (3 * 8192 + 256)

__global__ void __launch_bounds__(128, 3) flash_f16_kernel(
    const __half* __restrict__ Q16, const __half* __restrict__ K16,
    const __half* __restrict__ V16, const int* __restrict__ mask,
    __half* __restrict__ O16)
{
    extern __shared__ char smc[];
    char* Qs = smc;
    char* Ks = smc + 8192;
    char* Vs = smc + 16384;
    float* bias = (float*)(smc + 24576);

    const int qt = (gridDim.x - 1) - blockIdx.x;
    const int h = blockIdx.y, b = blockIdx.z;
    const int kvh = h >> 2;
    const int tid = threadIdx.x, warp = tid >> 5, lane = tid & 31;
    const int g = lane >> 2, t2 = (lane & 3) * 2;
    const float scale = 0.125f;
    const float slope = exp2f(-0.25f * (float)(h + 1));

    {
        const size_t base = (size_t)(b * SEQ + qt * 64) * 2048 + h * 64;
#pragma unroll
        for (int cc = 0; cc < 4; cc++) {
            const int c = tid + cc * 128;
            const int row = c >> 3, k8 = c & 7;
            cpasync16(Qs + swz(row * 128 + k8 * 16), Q16 + base + (size_t)row * 2048 + k8 * 8);
        }
        cp_commit(); cp_wait0();
        __syncthreads();
    }
    unsigned qf[4][4];
#pragma unroll
    for (int kc = 0; kc < 4; kc++)
        ldsm4(qf[kc], Qs + swz((warp * 16 + (lane & 15)) * 128 + kc * 32 + (lane >> 4) * 16));

    float o[8][4];
#pragma unroll
    for (int j = 0; j < 8; j++)
#pragma unroll
        for (int d = 0; d < 4; d++) o[j][d] = 0.0f;
    float m0 = -1e30f, m1 = -1e30f, l0 = 0.0f, l1 = 0.0f;
    const int qrow0 = qt * 64 + warp * 16 + g;

    for (int kt = 0; kt <= qt; kt++) {
        __syncthreads();
        {
            const size_t kbase = (size_t)(b * SEQ + kt * 64) * 512 + kvh * 64;
#pragma unroll
            for (int cc = 0; cc < 4; cc++) {
                const int c = tid + cc * 128;
                const int row = c >> 3, k8 = c & 7;
                const size_t gp = kbase + (size_t)row * 512 + k8 * 8;
                const unsigned so = swz(row * 128 + k8 * 16);
                cpasync16(Ks + so, K16 + gp);
                cpasync16(Vs + so, V16 + gp);
            }
        }
        if (tid < 64) bias[tid] = mask[b * SEQ + kt * 64 + tid] ? 0.0f : -1e30f;
        cp_commit(); cp_wait0();
        __syncthreads();

        float s[8][4];
#pragma unroll
        for (int j = 0; j < 8; j++)
#pragma unroll
            for (int d = 0; d < 4; d++) s[j][d] = 0.0f;

#pragma unroll
        for (int kc = 0; kc < 4; kc++)
#pragma unroll
            for (int jj = 0; jj < 4; jj++) {
                unsigned kt4[4];
                ldsm4(kt4, Ks + swz((jj * 16 + (lane & 15)) * 128 + kc * 32 + (lane >> 4) * 16));
                unsigned bfr[2];
                bfr[0] = kt4[0]; bfr[1] = kt4[2];
                mma16816h(s[2 * jj], qf[kc], bfr);
                bfr[0] = kt4[1]; bfr[1] = kt4[3];
                mma16816h(s[2 * jj + 1], qf[kc], bfr);
            }

#pragma unroll
        for (int j = 0; j < 8; j++) {
            const int kg = kt * 64 + j * 8 + t2;
            const float b0 = bias[j * 8 + t2];
            const float b1 = bias[j * 8 + t2 + 1];
            const float al0 = fmaf(slope, (float)kg, b0);
            const float al1 = fmaf(slope, (float)(kg + 1), b1);
            float v0 = fmaf(s[j][0], scale, al0);
            float v1 = fmaf(s[j][1], scale, al1);
            float v2 = fmaf(s[j][2], scale, al0);
            float v3 = fmaf(s[j][3], scale, al1);
            if (kg     > qrow0)     v0 = -1e30f;
            if (kg + 1 > qrow0)     v1 = -1e30f;
            if (kg     > qrow0 + 8) v2 = -1e30f;
            if (kg + 1 > qrow0 + 8) v3 = -1e30f;
            s[j][0] = v0; s[j][1] = v1; s[j][2] = v2; s[j][3] = v3;
        }

        float mx0 = -1e30f, mx1 = -1e30f;
#pragma unroll
        for (int j = 0; j < 8; j++) {
            mx0 = fmaxf(mx0, fmaxf(s[j][0], s[j][1]));
            mx1 = fmaxf(mx1, fmaxf(s[j][2], s[j][3]));
        }
        mx0 = fmaxf(mx0, __shfl_xor_sync(0xffffffffu, mx0, 1));
        mx0 = fmaxf(mx0, __shfl_xor_sync(0xffffffffu, mx0, 2));
        mx1 = fmaxf(mx1, __shfl_xor_sync(0xffffffffu, mx1, 1));
        mx1 = fmaxf(mx1, __shfl_xor_sync(0xffffffffu, mx1, 2));
        const float mn0 = fmaxf(m0, mx0), mn1 = fmaxf(m1, mx1);
        const float cr0 = __expf(m0 - mn0), cr1 = __expf(m1 - mn1);
        float ps0 = 0.0f, ps1 = 0.0f;
#pragma unroll
        for (int j = 0; j < 8; j++) {
            s[j][0] = __expf(s[j][0] - mn0);
            s[j][1] = __expf(s[j][1] - mn0);
            s[j][2] = __expf(s[j][2] - mn1);
            s[j][3] = __expf(s[j][3] - mn1);
            ps0 += s[j][0] + s[j][1];
            ps1 += s[j][2] + s[j][3];
        }
        ps0 += __shfl_xor_sync(0xffffffffu, ps0, 1);
        ps0 += __shfl_xor_sync(0xffffffffu, ps0, 2);
        ps1 += __shfl_xor_sync(0xffffffffu, ps1, 1);
        ps1 += __shfl_xor_sync(0xffffffffu, ps1, 2);
        l0 = l0 * cr0 + ps0; m0 = mn0;
        l1 = l1 * cr1 + ps1; m1 = mn1;
#pragma unroll
        for (int j = 0; j < 8; j++) {
            o[j][0] *= cr0; o[j][1] *= cr0;
            o[j][2] *= cr1; o[j][3] *= cr1;
        }

#pragma unroll
        for (int kc = 0; kc < 4; kc++) {
            unsigned pf[4];
            pf[0] = f2h2(s[2 * kc][0],     s[2 * kc][1]);
            pf[1] = f2h2(s[2 * kc][2],     s[2 * kc][3]);
            pf[2] = f2h2(s[2 * kc + 1][0], s[2 * kc + 1][1]);
            pf[3] = f2h2(s[2 * kc + 1][2], s[2 * kc + 1][3]);
#pragma unroll
            for (int jj = 0; jj < 4; jj++) {
                unsigned vt4[4];
                ldsm4t(vt4, Vs + swz((kc * 16 + (lane & 15)) * 128 + jj * 32 + (lane >> 4) * 16));
                unsigned bfr[2];
                bfr[0] = vt4[0]; bfr[1] = vt4[1];
                mma16816h(o[2 * jj], pf, bfr);
                bfr[0] = vt4[2]; bfr[1] = vt4[3];
                mma16816h(o[2 * jj + 1], pf, bfr);
            }
        }
    }

    const float inv0 = 1.0f / l0, inv1 = 1.0f / l1;
#pragma unroll
    for (int j = 0; j < 8; j++) {
        const size_t p0 = (size_t)(b * SEQ + qrow0) * 2048 + h * 64 + j * 8 + t2;
        *(unsigned*)(O16 + p0)            = f2h2(o[j][0] * inv0, o[j][1] * inv0);
        *(unsigned*)(O16 + p0 + 8 * 2048) = f2h2(o[j][2] * inv1, o[j][3] * inv1);
    }
}

// ---------------- host launcher -------------------------------------------
extern "C" void kernel_launch(void* const* d_in, const int* in_sizes, int n_in,
                              void* d_out, int out_size)
{
    const float* x    = (const float*)d_in[0];
    const int*   mask = (const int*)  d_in[1];
    const float* Wq   = (const float*)d_in[2];
    const float* Wk   = (const float*)d_in[3];
    const float* Wv   = (const float*)d_in[4];
    const float* Wo   = (const float*)d_in[5];
    float* out = (float*)d_out;

    void *pQ, *pK, *pV;
    void *px16, *pWq16, *pWk16, *pWv16, *pWo16, *pO16, *pQ16, *pK16, *pV16;
    cudaGetSymbolAddress(&pQ, g_Q);  cudaGetSymbolAddress(&pK, g_K);
    cudaGetSymbolAddress(&pV, g_V);
    cudaGetSymbolAddress(&px16, g_x16);
    cudaGetSymbolAddress(&pWq16, g_Wq16);
    cudaGetSymbolAddress(&pWk16, g_Wk16);
    cudaGetSymbolAddress(&pWv16, g_Wv16);
    cudaGetSymbolAddress(&pWo16, g_Wo16);
    cudaGetSymbolAddress(&pO16, g_O16);
    cudaGetSymbolAddress(&pQ16, g_Q16);
    cudaGetSymbolAddress(&pK16, g_K16);
    cudaGetSymbolAddress(&pV16, g_V16);

    init_freqs_kernel<<<1, 32>>>();

    // f16 casts
    split16_kernel<<<(MROWS * DMODEL / 4) / 256, 256>>>(x,  (__half*)px16,  MROWS * DMODEL / 4);
    split16_kernel<<<(DMODEL * 2048 / 4) / 256, 256>>>(Wq, (__half*)pWq16, DMODEL * 2048 / 4);
    split16_kernel<<<(DMODEL * 512  / 4) / 256, 256>>>(Wk, (__half*)pWk16, DMODEL * 512 / 4);
    split16_kernel<<<(DMODEL * 512  / 4) / 256, 256>>>(Wv, (__half*)pWv16, DMODEL * 512 / 4);
    split16_kernel<<<(2048 * DMODEL / 4) / 256, 256>>>(Wo, (__half*)pWo16, 2048 * DMODEL / 4);

    cudaFuncSetAttribute(gemm_f16, cudaFuncAttributeMaxDynamicSharedMemorySize, GEMM_SMEM);

    // QKV projections (f16 single-product)
    gemm_f16<<<dim3(2048 / 128, MROWS / 128), 256, GEMM_SMEM>>>(
        (const __half*)px16, (const __half*)pWq16, (float*)pQ, MROWS, 2048, DMODEL);
    gemm_f16<<<dim3(512 / 128, MROWS / 128), 256, GEMM_SMEM>>>(
        (const __half*)px16, (const __half*)pWk16, (float*)pK, MROWS, 512, DMODEL);
    gemm_f16<<<dim3(512 / 128, MROWS / 128), 256, GEMM_SMEM>>>(
        (const __half*)px16, (const __half*)pWv16, (float*)pV, MROWS, 512, DMODEL);

    // fused RoPE + f16 for Q and K; plain f16 for V
    rope_f16_kernel<<<(MROWS * NHEADS  * 32) / 256, 256>>>(
        (const float*)pQ, (__half*)pQ16, NHEADS * HDIM, NHEADS);
    rope_f16_kernel<<<(MROWS * KVHEADS * 32) / 256, 256>>>(
        (const float*)pK, (__half*)pK16, KVHEADS * HDIM, KVHEADS);
    split16_kernel<<<(MROWS * 512 / 4) / 256, 256>>>(
        (const float*)pV, (__half*)pV16, MROWS * 512 / 4);

    // Flash attention (full f16 single-plane)
    cudaFuncSetAttribute(flash_f16_kernel, cudaFuncAttributeMaxDynamicSharedMemorySize, FL_SMEM);
    flash_f16_kernel<<<dim3(SEQ / 64, NHEADS, BATCH), 128, FL_SMEM>>>(
        (const __half*)pQ16, (const __half*)pK16, (const __half*)pV16,
        mask, (__half*)pO16);

    // Output projection (f16 single-product)
    gemm_f16<<<dim3(2048 / 128, MROWS / 128), 256, GEMM_SMEM>>>(
        (const __half*)pO16, (const __half*)pWo16, out, MROWS, 2048, DMODEL);
}

// round 17
// speedup vs baseline: 2.5743x; 1.0002x over previous
#include <cuda_runtime.h>
#include <cuda_bf16.h>
#include <cuda_fp16.h>
#include <math.h>
#include <stdint.h>

#define BATCH   2
#define SEQ     2048
#define DMODEL  2048
#define NHEADS  32
#define HDIM    64
#define KVHEADS 8
#define MROWS   (BATCH*SEQ)          // 4096

// ---------------- scratch (device globals; no allocation allowed) ----------
__device__ float g_Q[MROWS * NHEADS * HDIM];
__device__ float g_K[MROWS * KVHEADS * HDIM];
__device__ float g_freqs[32];

// f16 planes
__device__ __half g_x16 [MROWS * DMODEL];
__device__ __half g_Wq16[DMODEL * 2048];
__device__ __half g_Wk16[DMODEL * 512];
__device__ __half g_Wv16[DMODEL * 512];
__device__ __half g_Wo16[2048 * DMODEL];
__device__ __half g_O16 [MROWS * 2048];
__device__ __half g_Q16 [MROWS * 2048];
__device__ __half g_K16 [MROWS * 512];
__device__ __half g_V16 [MROWS * 512];

// ---------------- RoPE frequency table -------------------------------------
__global__ void init_freqs_kernel() {
    int i = threadIdx.x;
    g_freqs[i] = (float)exp2(-(double)i * (13.287712379549449 / 32.0));
}

// ---------------- fp32 -> f16 single plane ----------------------------------
__global__ void __launch_bounds__(256) split16_kernel(
    const float* __restrict__ src, __half* __restrict__ dst, int n4)
{
    const int i = blockIdx.x * blockDim.x + threadIdx.x;
    if (i >= n4) return;
    const float4 f = ((const float4*)src)[i];
    __half2 a = __floats2half2_rn(f.x, f.y);
    __half2 b = __floats2half2_rn(f.z, f.w);
    uint2 v; v.x = *(unsigned*)&a; v.y = *(unsigned*)&b;
    *(uint2*)(dst + 4 * (size_t)i) = v;
}

// ---------------- PTX helpers ----------------------------------------------
__device__ __forceinline__ void cpasync16(void* s, const void* g) {
    unsigned sa = (unsigned)__cvta_generic_to_shared(s);
    asm volatile("cp.async.cg.shared.global [%0], [%1], 16;\n" :: "r"(sa), "l"(g));
}
__device__ __forceinline__ void cp_commit() {
    asm volatile("cp.async.commit_group;\n" ::: "memory");
}
__device__ __forceinline__ void cp_wait0() {
    asm volatile("cp.async.wait_group 0;\n" ::: "memory");
}
__device__ __forceinline__ void cp_wait1() {
    asm volatile("cp.async.wait_group 1;\n" ::: "memory");
}
__device__ __forceinline__ void ldsm4(unsigned* r, const void* p) {
    unsigned a = (unsigned)__cvta_generic_to_shared(p);
    asm volatile("ldmatrix.sync.aligned.m8n8.x4.shared.b16 {%0,%1,%2,%3}, [%4];"
                 : "=r"(r[0]), "=r"(r[1]), "=r"(r[2]), "=r"(r[3]) : "r"(a));
}
__device__ __forceinline__ void ldsm4t(unsigned* r, const void* p) {
    unsigned a = (unsigned)__cvta_generic_to_shared(p);
    asm volatile("ldmatrix.sync.aligned.m8n8.x4.trans.shared.b16 {%0,%1,%2,%3}, [%4];"
                 : "=r"(r[0]), "=r"(r[1]), "=r"(r[2]), "=r"(r[3]) : "r"(a));
}
__device__ __forceinline__ void mma16816h(float* d, const unsigned* a, const unsigned* b) {
    asm volatile("mma.sync.aligned.m16n8k16.row.col.f32.f16.f16.f32 "
                 "{%0,%1,%2,%3},{%4,%5,%6,%7},{%8,%9},{%0,%1,%2,%3};"
                 : "+f"(d[0]), "+f"(d[1]), "+f"(d[2]), "+f"(d[3])
                 : "r"(a[0]), "r"(a[1]), "r"(a[2]), "r"(a[3]), "r"(b[0]), "r"(b[1]));
}
__device__ __forceinline__ unsigned swz(unsigned o) { return o ^ ((o >> 3) & 0x70); }

__device__ __forceinline__ unsigned f2h2(float x, float y) {
    __half2 h = __floats2half2_rn(x, y);
    return *(unsigned*)&h;
}

// ---------------- f16 single-product GEMM (fp32 out) -------------------------
#define SA_STRIDE 56
#define SB_STRIDE 136
#define SA_PLANE  (128 * SA_STRIDE)
#define SB_PLANE  (32 * SB_STRIDE)
#define STAGE_ELEMS (SA_PLANE + SB_PLANE)
#define GEMM_SMEM (3 * STAGE_ELEMS * 2)

#define GEMM_BODY(EPILOGUE)                                                     \
    extern __shared__ __half sm[];                                              \
    const int tid  = threadIdx.x;                                               \
    const int warp = tid >> 5, lane = tid & 31;                                 \
    const int bm = blockIdx.y * 128, bn = blockIdx.x * 128;                     \
    const int wm = (warp >> 2) * 64, wn = (warp & 3) * 32;                      \
    float acc[4][4][4];                                                         \
    _Pragma("unroll")                                                           \
    for (int i = 0; i < 4; i++)                                                 \
        _Pragma("unroll")                                                       \
        for (int j = 0; j < 4; j++)                                             \
            _Pragma("unroll")                                                   \
            for (int d = 0; d < 4; d++) acc[i][j][d] = 0.0f;                    \
    const int kIters = K >> 5;                                                  \
    LOAD_STAGE(0, 0);                                                           \
    LOAD_STAGE(1, 32);                                                          \
    for (int it = 0; it < kIters; it++) {                                       \
        const int s = it % 3;                                                   \
        if (it + 1 < kIters) cp_wait1(); else cp_wait0();                       \
        __syncthreads();                                                        \
        if (it + 2 < kIters) LOAD_STAGE((it + 2) % 3, (it + 2) * 32);           \
        const __half* Sa = sm + s * STAGE_ELEMS;                                \
        const __half* Sb = Sa + SA_PLANE;                                       \
        _Pragma("unroll")                                                       \
        for (int kk = 0; kk < 2; kk++) {                                        \
            unsigned af[4][4];                                                  \
            _Pragma("unroll")                                                   \
            for (int i = 0; i < 4; i++)                                         \
                ldsm4(af[i], Sa + (wm + i * 16 + (lane & 15)) * SA_STRIDE       \
                              + kk * 16 + (lane >> 4) * 8);                     \
            unsigned bf[4][2];                                                  \
            _Pragma("unroll")                                                   \
            for (int jj = 0; jj < 2; jj++) {                                    \
                unsigned t[4];                                                  \
                ldsm4t(t, Sb + (kk * 16 + (lane & 15)) * SB_STRIDE              \
                           + wn + jj * 16 + (lane >> 4) * 8);                   \
                bf[2 * jj][0] = t[0]; bf[2 * jj][1] = t[1];                     \
                bf[2 * jj + 1][0] = t[2]; bf[2 * jj + 1][1] = t[3];             \
            }                                                                   \
            _Pragma("unroll")                                                   \
            for (int i = 0; i < 4; i++)                                         \
                _Pragma("unroll")                                               \
                for (int j = 0; j < 4; j++)                                     \
                    mma16816h(acc[i][j], af[i], bf[j]);                         \
        }                                                                       \
    }                                                                           \
    EPILOGUE

#define LOAD_STAGE(s, k0) do {                                                  \
        __half* Sa = sm + (s) * STAGE_ELEMS;                                    \
        __half* Sb = Sa + SA_PLANE;                                             \
        _Pragma("unroll")                                                       \
        for (int cc = 0; cc < 2; cc++) {                                        \
            const int c  = tid + cc * 256;                                      \
            const int ar = c >> 2, ac = c & 3;                                  \
            cpasync16(Sa + ar * SA_STRIDE + ac * 8,                             \
                      A + (size_t)(bm + ar) * K + (k0) + ac * 8);               \
            const int br = c >> 4, bc = c & 15;                                 \
            cpasync16(Sb + br * SB_STRIDE + bc * 8,                             \
                      B + (size_t)((k0) + br) * N + bn + bc * 8);               \
        }                                                                       \
        cp_commit();                                                            \
    } while (0)

__global__ void __launch_bounds__(256) gemm_f16(
    const __half* __restrict__ A, const __half* __restrict__ B,
    float* __restrict__ C, int M, int N, int K)
{
    GEMM_BODY({
#pragma unroll
        for (int i = 0; i < 4; i++)
#pragma unroll
            for (int j = 0; j < 4; j++) {
                const int r = bm + wm + i * 16 + (lane >> 2);
                const int c = bn + wn + j * 8 + (lane & 3) * 2;
                *(float2*)(C + (size_t)r * N + c)       = make_float2(acc[i][j][0], acc[i][j][1]);
                *(float2*)(C + (size_t)(r + 8) * N + c) = make_float2(acc[i][j][2], acc[i][j][3]);
            }
    })
}

// f16-output variant (for V projection: feeds flash directly)
__global__ void __launch_bounds__(256) gemm_f16h(
    const __half* __restrict__ A, const __half* __restrict__ B,
    __half* __restrict__ C, int M, int N, int K)
{
    GEMM_BODY({
#pragma unroll
        for (int i = 0; i < 4; i++)
#pragma unroll
            for (int j = 0; j < 4; j++) {
                const int r = bm + wm + i * 16 + (lane >> 2);
                const int c = bn + wn + j * 8 + (lane & 3) * 2;
                *(unsigned*)(C + (size_t)r * N + c)       = f2h2(acc[i][j][0], acc[i][j][1]);
                *(unsigned*)(C + (size_t)(r + 8) * N + c) = f2h2(acc[i][j][2], acc[i][j][3]);
            }
    })
}

// ---------------- fused RoPE + f16 convert ----------------------------------
__global__ void rope_f16_kernel(
    const float* __restrict__ buf, __half* __restrict__ dst, int rowlen, int heads)
{
    const int idx = blockIdx.x * blockDim.x + threadIdx.x;
    const int total = MROWS * heads * 32;
    if (idx >= total) return;
    const int j  = idx & 31;
    const int t1 = idx >> 5;
    const int h  = t1 % heads;
    const int r  = t1 / heads;
    const float tn = (float)(r & (SEQ - 1));

    const size_t base = (size_t)r * rowlen + h * HDIM;
    const float x1 = buf[base + j];
    const float x2 = buf[base + j + 32];

    const float a1 = tn * g_freqs[j >> 1];
    const float a2 = tn * g_freqs[16 + (j >> 1)];
    float s1, c1, s2, c2;
    sincosf(a1, &s1, &c1);
    sincosf(a2, &s2, &c2);
    dst[base + j]      = __float2half_rn(x1 * c1 - x2 * s1);
    dst[base + j + 32] = __float2half_rn(x1 * s2 + x2 * c2);
}

// ---------------- Flash attention, f16, KT=128 ------------------------------
// smem: Qs 8KB + Ks 16KB + Vs 16KB + bias 512B = 41472 B
#define FL_SMEM (8192 + 16384 + 16384 + 512)

__global__ void __launch_bounds__(128, 3) flash_f16_kernel(
    const __half* __restrict__ Q16, const __half* __restrict__ K16,
    const __half* __restrict__ V16, const int* __restrict__ mask,
    __half* __restrict__ O16)
{
    extern __shared__ char smc[];
    char* Qs = smc;
    char* Ks = smc + 8192;       // 128 rows x 128B
    char* Vs = smc + 24576;      // 128 rows x 128B
    float* bias = (float*)(smc + 40960);

    const int qt = (gridDim.x - 1) - blockIdx.x;
    const int h = blockIdx.y, b = blockIdx.z;
    const int kvh = h >> 2;
    const int tid = threadIdx.x, warp = tid >> 5, lane = tid & 31;
    const int g = lane >> 2, t2 = (lane & 3) * 2;
    const float scale = 0.125f;
    const float slope = exp2f(-0.25f * (float)(h + 1));

    // ---- load Q tile ----
    {
        const size_t base = (size_t)(b * SEQ + qt * 64) * 2048 + h * 64;
#pragma unroll
        for (int cc = 0; cc < 4; cc++) {
            const int c = tid + cc * 128;
            const int row = c >> 3, k8 = c & 7;
            cpasync16(Qs + swz(row * 128 + k8 * 16), Q16 + base + (size_t)row * 2048 + k8 * 8);
        }
        cp_commit(); cp_wait0();
        __syncthreads();
    }
    unsigned qf[4][4];
#pragma unroll
    for (int kc = 0; kc < 4; kc++)
        ldsm4(qf[kc], Qs + swz((warp * 16 + (lane & 15)) * 128 + kc * 32 + (lane >> 4) * 16));

    float o[8][4];
#pragma unroll
    for (int j = 0; j < 8; j++)
#pragma unroll
        for (int d = 0; d < 4; d++) o[j][d] = 0.0f;
    float m0 = -1e30f, m1 = -1e30f, l0 = 0.0f, l1 = 0.0f;
    const int qrow0 = qt * 64 + warp * 16 + g;
    const int qlimit = qt * 64 + 63;

    const int nk2 = (qt + 2) >> 1;   // number of 128-key blocks covering causal range

    for (int kt2 = 0; kt2 < nk2; kt2++) {
        const bool h1live = (kt2 * 128 + 64) <= qlimit;
        __syncthreads();
        {
            const size_t kbase = (size_t)(b * SEQ + kt2 * 128) * 512 + kvh * 64;
#pragma unroll
            for (int cc = 0; cc < 8; cc++) {
                const int c = tid + cc * 128;
                const int row = c >> 3, k8 = c & 7;
                const size_t gp = kbase + (size_t)row * 512 + k8 * 8;
                const unsigned so = swz(row * 128 + k8 * 16);
                cpasync16(Ks + so, K16 + gp);
                cpasync16(Vs + so, V16 + gp);
            }
        }
        bias[tid] = mask[b * SEQ + kt2 * 128 + tid] ? 0.0f : -1e30f;
        cp_commit(); cp_wait0();
        __syncthreads();

        // ---- S = Q K^T over 128 keys ----
        float s[16][4];
#pragma unroll
        for (int j = 0; j < 16; j++)
#pragma unroll
            for (int d = 0; d < 4; d++) s[j][d] = 0.0f;

#pragma unroll
        for (int kc = 0; kc < 4; kc++)
#pragma unroll
            for (int jj = 0; jj < 4; jj++) {
                unsigned kt4[4];
                ldsm4(kt4, Ks + swz((jj * 16 + (lane & 15)) * 128 + kc * 32 + (lane >> 4) * 16));
                unsigned bfr[2];
                bfr[0] = kt4[0]; bfr[1] = kt4[2];
                mma16816h(s[2 * jj], qf[kc], bfr);
                bfr[0] = kt4[1]; bfr[1] = kt4[3];
                mma16816h(s[2 * jj + 1], qf[kc], bfr);
            }
        if (h1live) {
#pragma unroll
            for (int kc = 0; kc < 4; kc++)
#pragma unroll
                for (int jj = 0; jj < 4; jj++) {
                    unsigned kt4[4];
                    ldsm4(kt4, Ks + swz(((64 + jj * 16) + (lane & 15)) * 128 + kc * 32 + (lane >> 4) * 16));
                    unsigned bfr[2];
                    bfr[0] = kt4[0]; bfr[1] = kt4[2];
                    mma16816h(s[8 + 2 * jj], qf[kc], bfr);
                    bfr[0] = kt4[1]; bfr[1] = kt4[3];
                    mma16816h(s[8 + 2 * jj + 1], qf[kc], bfr);
                }
        }

        // ---- scale + ALiBi + causal + pad (16 j-groups) ----
        const int jmax = h1live ? 16 : 8;
#pragma unroll
        for (int j = 0; j < 16; j++) {
            if (j >= jmax) { s[j][0] = s[j][1] = s[j][2] = s[j][3] = -1e30f; continue; }
            const int kg = kt2 * 128 + j * 8 + t2;
            const float b0 = bias[j * 8 + t2];
            const float b1 = bias[j * 8 + t2 + 1];
            const float al0 = fmaf(slope, (float)kg, b0);
            const float al1 = fmaf(slope, (float)(kg + 1), b1);
            float v0 = fmaf(s[j][0], scale, al0);
            float v1 = fmaf(s[j][1], scale, al1);
            float v2 = fmaf(s[j][2], scale, al0);
            float v3 = fmaf(s[j][3], scale, al1);
            if (kg     > qrow0)     v0 = -1e30f;
            if (kg + 1 > qrow0)     v1 = -1e30f;
            if (kg     > qrow0 + 8) v2 = -1e30f;
            if (kg + 1 > qrow0 + 8) v3 = -1e30f;
            s[j][0] = v0; s[j][1] = v1; s[j][2] = v2; s[j][3] = v3;
        }

        // ---- single online-softmax update for 128 keys ----
        float mx0 = -1e30f, mx1 = -1e30f;
#pragma unroll
        for (int j = 0; j < 16; j++) {
            mx0 = fmaxf(mx0, fmaxf(s[j][0], s[j][1]));
            mx1 = fmaxf(mx1, fmaxf(s[j][2], s[j][3]));
        }
        mx0 = fmaxf(mx0, __shfl_xor_sync(0xffffffffu, mx0, 1));
        mx0 = fmaxf(mx0, __shfl_xor_sync(0xffffffffu, mx0, 2));
        mx1 = fmaxf(mx1, __shfl_xor_sync(0xffffffffu, mx1, 1));
        mx1 = fmaxf(mx1, __shfl_xor_sync(0xffffffffu, mx1, 2));
        const float mn0 = fmaxf(m0, mx0), mn1 = fmaxf(m1, mx1);
        const float cr0 = __expf(m0 - mn0), cr1 = __expf(m1 - mn1);
        float ps0 = 0.0f, ps1 = 0.0f;
#pragma unroll
        for (int j = 0; j < 16; j++) {
            s[j][0] = __expf(s[j][0] - mn0);
            s[j][1] = __expf(s[j][1] - mn0);
            s[j][2] = __expf(s[j][2] - mn1);
            s[j][3] = __expf(s[j][3] - mn1);
            ps0 += s[j][0] + s[j][1];
            ps1 += s[j][2] + s[j][3];
        }
        ps0 += __shfl_xor_sync(0xffffffffu, ps0, 1);
        ps0 += __shfl_xor_sync(0xffffffffu, ps0, 2);
        ps1 += __shfl_xor_sync(0xffffffffu, ps1, 1);
        ps1 += __shfl_xor_sync(0xffffffffu, ps1, 2);
        l0 = l0 * cr0 + ps0; m0 = mn0;
        l1 = l1 * cr1 + ps1; m1 = mn1;
#pragma unroll
        for (int j = 0; j < 8; j++) {
            o[j][0] *= cr0; o[j][1] *= cr0;
            o[j][2] *= cr1; o[j][3] *= cr1;
        }

        // ---- O += P V over 128 keys ----
        const int kcmax = h1live ? 8 : 4;
#pragma unroll
        for (int kc = 0; kc < 8; kc++) {
            if (kc >= kcmax) break;
            unsigned pf[4];
            pf[0] = f2h2(s[2 * kc][0],     s[2 * kc][1]);
            pf[1] = f2h2(s[2 * kc][2],     s[2 * kc][3]);
            pf[2] = f2h2(s[2 * kc + 1][0], s[2 * kc + 1][1]);
            pf[3] = f2h2(s[2 * kc + 1][2], s[2 * kc + 1][3]);
#pragma unroll
            for (int jj = 0; jj < 4; jj++) {
                unsigned vt4[4];
                ldsm4t(vt4, Vs + swz((kc * 16 + (lane & 15)) * 128 + jj * 32 + (lane >> 4) * 16));
                unsigned bfr[2];
                bfr[0] = vt4[0]; bfr[1] = vt4[1];
                mma16816h(o[2 * jj], pf, bfr);
                bfr[0] = vt4[2]; bfr[1] = vt4[3];
                mma16816h(o[2 * jj + 1], pf, bfr);
            }
        }
    }

    // ---- epilogue ----
    const float inv0 = 1.0f / l0, inv1 = 1.0f / l1;
#pragma unroll
    for (int j = 0; j < 8; j++) {
        const size_t p0 = (size_t)(b * SEQ + qrow0) * 2048 + h * 64 + j * 8 + t2;
        *(unsigned*)(O16 + p0)            = f2h2(o[j][0] * inv0, o[j][1] * inv0);
        *(unsigned*)(O16 + p0 + 8 * 2048) = f2h2(o[j][2] * inv1, o[j][3] * inv1);
    }
}

// ---------------- host launcher -------------------------------------------
extern "C" void kernel_launch(void* const* d_in, const int* in_sizes, int n_in,
                              void* d_out, int out_size)
{
    const float* x    = (const float*)d_in[0];
    const int*   mask = (const int*)  d_in[1];
    const float* Wq   = (const float*)d_in[2];
    const float* Wk   = (const float*)d_in[3];
    const float* Wv   = (const float*)d_in[4];
    const float* Wo   = (const float*)d_in[5];
    float* out = (float*)d_out;

    void *pQ, *pK;
    void *px16, *pWq16, *pWk16, *pWv16, *pWo16, *pO16, *pQ16, *pK16, *pV16;
    cudaGetSymbolAddress(&pQ, g_Q);  cudaGetSymbolAddress(&pK, g_K);
    cudaGetSymbolAddress(&px16, g_x16);
    cudaGetSymbolAddress(&pWq16, g_Wq16);
    cudaGetSymbolAddress(&pWk16, g_Wk16);
    cudaGetSymbolAddress(&pWv16, g_Wv16);
    cudaGetSymbolAddress(&pWo16, g_Wo16);
    cudaGetSymbolAddress(&pO16, g_O16);
    cudaGetSymbolAddress(&pQ16, g_Q16);
    cudaGetSymbolAddress(&pK16, g_K16);
    cudaGetSymbolAddress(&pV16, g_V16);

    init_freqs_kernel<<<1, 32>>>();

    // f16 casts
    split16_kernel<<<(MROWS * DMODEL / 4) / 256, 256>>>(x,  (__half*)px16,  MROWS * DMODEL / 4);
    split16_kernel<<<(DMODEL * 2048 / 4) / 256, 256>>>(Wq, (__half*)pWq16, DMODEL * 2048 / 4);
    split16_kernel<<<(DMODEL * 512  / 4) / 256, 256>>>(Wk, (__half*)pWk16, DMODEL * 512 / 4);
    split16_kernel<<<(DMODEL * 512  / 4) / 256, 256>>>(Wv, (__half*)pWv16, DMODEL * 512 / 4);
    split16_kernel<<<(2048 * DMODEL / 4) / 256, 256>>>(Wo, (__half*)pWo16, 2048 * DMODEL / 4);

    cudaFuncSetAttribute(gemm_f16,  cudaFuncAttributeMaxDynamicSharedMemorySize, GEMM_SMEM);
    cudaFuncSetAttribute(gemm_f16h, cudaFuncAttributeMaxDynamicSharedMemorySize, GEMM_SMEM);

    // QKV projections
    gemm_f16<<<dim3(2048 / 128, MROWS / 128), 256, GEMM_SMEM>>>(
        (const __half*)px16, (const __half*)pWq16, (float*)pQ, MROWS, 2048, DMODEL);
    gemm_f16<<<dim3(512 / 128, MROWS / 128), 256, GEMM_SMEM>>>(
        (const __half*)px16, (const __half*)pWk16, (float*)pK, MROWS, 512, DMODEL);
    gemm_f16h<<<dim3(512 / 128, MROWS / 128), 256, GEMM_SMEM>>>(
        (const __half*)px16, (const __half*)pWv16, (__half*)pV16, MROWS, 512, DMODEL);

    // fused RoPE + f16 for Q and K
    rope_f16_kernel<<<(MROWS * NHEADS  * 32) / 256, 256>>>(
        (const float*)pQ, (__half*)pQ16, NHEADS * HDIM, NHEADS);
    rope_f16_kernel<<<(MROWS * KVHEADS * 32) / 256, 256>>>(
        (const float*)pK, (__half*)pK16, KVHEADS * HDIM, KVHEADS);

    // Flash attention (f16, KT=128)
    cudaFuncSetAttribute(flash_f16_kernel, cudaFuncAttributeMaxDynamicSharedMemorySize, FL_SMEM);
    flash_f16_kernel<<<dim3(SEQ / 64, NHEADS, BATCH), 128, FL_SMEM>>>(
        (const __half*)pQ16, (const __half*)pK16, (const __half*)pV16,
        mask, (__half*)pO16);

    // Output projection
    gemm_f16<<<dim3(2048 / 128, MROWS / 128), 256, GEMM_SMEM>>>(
        (const __half*)pO16, (const __half*)pWo16, out, MROWS, 2048, DMODEL);
}